// round 1
// baseline (speedup 1.0000x reference)
#include <cuda_runtime.h>
#include <math.h>

#define NGENE 50000
#define NDIS  25000
#define FGENE 512
#define FDIS  256
#define CH    128
#define NE    150000

// ---------------- scratch (static device globals; no allocation) ----------------
__device__ float  g_xs[(size_t)NGENE * 512];      // xs = x_src @ Ws  [Ns, H*C]
__device__ float  g_agg[(size_t)NGENE * CH];      // per-dst aggregation (head-mean folded)
__device__ float  g_ls[NGENE * 4];                // per-src attention logits (src part)
__device__ float  g_ld[NGENE * 4];                // per-dst attention logits (dst part)
__device__ float  g_logits[(NE + NGENE) * 4];     // per-edge logits, then p
__device__ float  g_m[NGENE * 4];                 // segment max
__device__ float  g_denom[NGENE * 4];             // segment sum
__device__ float  g_wld[512];                     // folded Wd @ a_d  [128,4]
__device__ double g_sum[CH];
__device__ double g_sumsq[CH];

// ---------------- helpers ----------------
__device__ __forceinline__ void atomicMaxF(float* addr, float v) {
    if (v >= 0.f) atomicMax((int*)addr, __float_as_int(v));
    else          atomicMin((unsigned int*)addr, __float_as_uint(v));
}

__device__ __forceinline__ float leaky(float x) { return x > 0.f ? x : 0.2f * x; }

// ---------------- SGEMM: C[M,N] = A[M,K] @ B[K,N] (+bias, +relu) ----------------
// 128x128 tile, BK=8, 256 threads, 8x8 per thread. N % 128 == 0, K % 8 == 0.
__global__ __launch_bounds__(256, 2)
void sgemm_kernel(const float* __restrict__ A, const float* __restrict__ B,
                  const float* __restrict__ bias, float* __restrict__ C,
                  int M, int N, int K, int flags)   // flags bit0=bias, bit1=relu
{
    __shared__ float As[8][132];
    __shared__ float Bs[8][132];
    const int tid = threadIdx.x;
    const int bm = blockIdx.y * 128;
    const int bn = blockIdx.x * 128;

    const int arow = tid >> 1;            // 0..127
    const int akol = (tid & 1) * 4;       // 0 or 4
    const int bkrow = tid >> 5;           // 0..7
    const int bcol = (tid & 31) * 4;      // 0..124

    const int tx = tid & 15, ty = tid >> 4;
    const int tm = ty * 8, tn = tx * 8;

    float acc[8][8];
#pragma unroll
    for (int i = 0; i < 8; i++)
#pragma unroll
        for (int j = 0; j < 8; j++) acc[i][j] = 0.f;

    const int gm = bm + arow;
    for (int k0 = 0; k0 < K; k0 += 8) {
        float4 av = make_float4(0.f, 0.f, 0.f, 0.f);
        if (gm < M) av = *(const float4*)(A + (size_t)gm * K + k0 + akol);
        As[akol + 0][arow] = av.x;
        As[akol + 1][arow] = av.y;
        As[akol + 2][arow] = av.z;
        As[akol + 3][arow] = av.w;
        float4 bv = *(const float4*)(B + (size_t)(k0 + bkrow) * N + bn + bcol);
        *(float4*)&Bs[bkrow][bcol] = bv;
        __syncthreads();
#pragma unroll
        for (int kk = 0; kk < 8; kk++) {
            float a[8], b[8];
            *(float4*)(a)     = *(const float4*)&As[kk][tm];
            *(float4*)(a + 4) = *(const float4*)&As[kk][tm + 4];
            *(float4*)(b)     = *(const float4*)&Bs[kk][tn];
            *(float4*)(b + 4) = *(const float4*)&Bs[kk][tn + 4];
#pragma unroll
            for (int i = 0; i < 8; i++)
#pragma unroll
                for (int j = 0; j < 8; j++) acc[i][j] += a[i] * b[j];
        }
        __syncthreads();
    }

    for (int i = 0; i < 8; i++) {
        int r = bm + tm + i;
        if (r >= M) break;
        float* crow = C + (size_t)r * N + bn + tn;
#pragma unroll
        for (int j = 0; j < 8; j += 4) {
            float4 v = make_float4(acc[i][j], acc[i][j + 1], acc[i][j + 2], acc[i][j + 3]);
            if (flags & 1) {
                const float* bp = bias + bn + tn + j;
                v.x += bp[0]; v.y += bp[1]; v.z += bp[2]; v.w += bp[3];
            }
            if (flags & 2) {
                v.x = fmaxf(v.x, 0.f); v.y = fmaxf(v.y, 0.f);
                v.z = fmaxf(v.z, 0.f); v.w = fmaxf(v.w, 0.f);
            }
            *(float4*)(crow + j) = v;
        }
    }
}

// ---------------- BatchNorm ----------------
__global__ void zero_stats_kernel() {
    int c = threadIdx.x;
    g_sum[c] = 0.0; g_sumsq[c] = 0.0;
}

__global__ void colsum_kernel(const float* __restrict__ h, int M) {
    int c = threadIdx.x;   // 128
    float s = 0.f, q = 0.f;
    for (int r = blockIdx.x; r < M; r += gridDim.x) {
        float v = h[(size_t)r * CH + c];
        s += v; q += v * v;
    }
    atomicAdd(&g_sum[c], (double)s);
    atomicAdd(&g_sumsq[c], (double)q);
}

__global__ void bn_kernel(float* __restrict__ h, int M,
                          const float* __restrict__ gamma, const float* __restrict__ beta) {
    int idx = blockIdx.x * blockDim.x + threadIdx.x;
    if (idx >= M * CH) return;
    int c = idx & 127;
    double mu = g_sum[c] / M;
    double var = g_sumsq[c] / M - mu * mu;
    float sc = gamma[c] * rsqrtf((float)var + 1e-5f);
    h[idx] = (h[idx] - (float)mu) * sc + beta[c];
}

// ---------------- GAT pieces ----------------
// w_ld[k][h] = sum_c Wd[k, h*128+c] * a_d[h, c]
__global__ void wld_kernel(const float* __restrict__ Wd, const float* __restrict__ ad) {
    int t = blockIdx.x * blockDim.x + threadIdx.x;
    if (t >= 512) return;
    int k = t >> 2, h = t & 3;
    float s = 0.f;
    for (int c = 0; c < 128; c++)
        s += Wd[(size_t)k * 512 + h * 128 + c] * ad[h * 128 + c];
    g_wld[k * 4 + h] = s;
}

// ls[i,h] = sum_c xs[i,h,c] * a_s[h,c]   (one warp per node)
__global__ void ls_kernel(const float* __restrict__ a_s, int N) {
    int w = (blockIdx.x * blockDim.x + threadIdx.x) >> 5;
    int lane = threadIdx.x & 31;
    if (w >= N) return;
    const float4* xr = (const float4*)g_xs + (size_t)w * 128;
    int head = lane >> 3, sub = lane & 7;
    const float4* ar = (const float4*)a_s + head * 32;
    float acc = 0.f;
#pragma unroll
    for (int j = 0; j < 4; j++) {
        float4 x = xr[lane * 4 + j];
        float4 a = ar[sub * 4 + j];
        acc += x.x * a.x + x.y * a.y + x.z * a.z + x.w * a.w;
    }
    acc += __shfl_xor_sync(0xffffffffu, acc, 4);
    acc += __shfl_xor_sync(0xffffffffu, acc, 2);
    acc += __shfl_xor_sync(0xffffffffu, acc, 1);
    if (sub == 0) g_ls[w * 4 + head] = acc;
}

// ld[i,h] = x_dst[i] @ w_ld[:,h]   (one warp per node)
__global__ void ld_kernel(const float* __restrict__ x, int N) {
    int w = (blockIdx.x * blockDim.x + threadIdx.x) >> 5;
    int lane = threadIdx.x & 31;
    if (w >= N) return;
    const float* row = x + (size_t)w * CH;
    float h0 = 0.f, h1 = 0.f, h2 = 0.f, h3 = 0.f;
#pragma unroll
    for (int j = 0; j < 4; j++) {
        int k = lane + 32 * j;
        float v = row[k];
        float4 wv = ((const float4*)g_wld)[k];
        h0 += v * wv.x; h1 += v * wv.y; h2 += v * wv.z; h3 += v * wv.w;
    }
#pragma unroll
    for (int off = 16; off > 0; off >>= 1) {
        h0 += __shfl_xor_sync(0xffffffffu, h0, off);
        h1 += __shfl_xor_sync(0xffffffffu, h1, off);
        h2 += __shfl_xor_sync(0xffffffffu, h2, off);
        h3 += __shfl_xor_sync(0xffffffffu, h3, off);
    }
    if (lane == 0) ((float4*)g_ld)[w] = make_float4(h0, h1, h2, h3);
}

__global__ void gat_init_kernel(int n_dst) {
    int stride = gridDim.x * blockDim.x;
    int start = blockIdx.x * blockDim.x + threadIdx.x;
    float ninf = __int_as_float(0xff800000);
    for (int i = start; i < n_dst * CH; i += stride) g_agg[i] = 0.f;
    for (int i = start; i < n_dst * 4; i += stride) { g_m[i] = ninf; g_denom[i] = 0.f; }
}

// pass1: logits + segment max
__global__ void gat_pass1_kernel(const int* __restrict__ src, const int* __restrict__ dst,
                                 int E, int n_loop) {
    int e = blockIdx.x * blockDim.x + threadIdx.x;
    if (e >= E + n_loop) return;
    int s, d; bool mask;
    if (e < E) { s = src[e]; d = dst[e]; mask = (s != d); }
    else       { s = d = e - E; mask = true; }
    float4 a = ((const float4*)g_ls)[s];
    float4 b = ((const float4*)g_ld)[d];
    float l0 = leaky(a.x + b.x), l1 = leaky(a.y + b.y);
    float l2 = leaky(a.z + b.z), l3 = leaky(a.w + b.w);
    if (!mask) { l0 = l1 = l2 = l3 = -1e30f; }
    ((float4*)g_logits)[e] = make_float4(l0, l1, l2, l3);
    atomicMaxF(&g_m[d * 4 + 0], l0);
    atomicMaxF(&g_m[d * 4 + 1], l1);
    atomicMaxF(&g_m[d * 4 + 2], l2);
    atomicMaxF(&g_m[d * 4 + 3], l3);
}

// pass2: p = exp(logit - m[dst]) * mask ; segment sum
__global__ void gat_pass2_kernel(const int* __restrict__ src, const int* __restrict__ dst,
                                 int E, int n_loop) {
    int e = blockIdx.x * blockDim.x + threadIdx.x;
    if (e >= E + n_loop) return;
    int d; bool mask;
    if (e < E) { int s = src[e]; d = dst[e]; mask = (s != d); }
    else       { d = e - E; mask = true; }
    float4 L = ((const float4*)g_logits)[e];
    float4 M4 = ((const float4*)g_m)[d];
    float p0 = mask ? expf(L.x - M4.x) : 0.f;
    float p1 = mask ? expf(L.y - M4.y) : 0.f;
    float p2 = mask ? expf(L.z - M4.z) : 0.f;
    float p3 = mask ? expf(L.w - M4.w) : 0.f;
    ((float4*)g_logits)[e] = make_float4(p0, p1, p2, p3);
    atomicAdd(&g_denom[d * 4 + 0], p0);
    atomicAdd(&g_denom[d * 4 + 1], p1);
    atomicAdd(&g_denom[d * 4 + 2], p2);
    atomicAdd(&g_denom[d * 4 + 3], p3);
}

// pass3: agg[dst] += (1/4) * sum_h alpha_h * xs[src,h,:]   (one warp per edge)
__global__ void gat_pass3_kernel(const int* __restrict__ src, const int* __restrict__ dst,
                                 int E, int n_loop) {
    int w = (blockIdx.x * blockDim.x + threadIdx.x) >> 5;
    int lane = threadIdx.x & 31;
    if (w >= E + n_loop) return;
    int s, d;
    if (w < E) { s = src[w]; d = dst[w]; }
    else       { s = d = w - E; }
    float4 P = ((const float4*)g_logits)[w];
    float4 D = ((const float4*)g_denom)[d];
    float a0 = 0.25f * P.x / (D.x > 0.f ? D.x : 1.f);
    float a1 = 0.25f * P.y / (D.y > 0.f ? D.y : 1.f);
    float a2 = 0.25f * P.z / (D.z > 0.f ? D.z : 1.f);
    float a3 = 0.25f * P.w / (D.w > 0.f ? D.w : 1.f);
    const float4* xr = (const float4*)g_xs + (size_t)s * 128;
    float4 x0 = xr[lane], x1 = xr[32 + lane], x2 = xr[64 + lane], x3 = xr[96 + lane];
    float r0 = a0 * x0.x + a1 * x1.x + a2 * x2.x + a3 * x3.x;
    float r1 = a0 * x0.y + a1 * x1.y + a2 * x2.y + a3 * x3.y;
    float r2 = a0 * x0.z + a1 * x1.z + a2 * x2.z + a3 * x3.z;
    float r3 = a0 * x0.w + a1 * x1.w + a2 * x2.w + a3 * x3.w;
    float* out = g_agg + (size_t)d * CH + lane * 4;
    asm volatile("red.global.add.v4.f32 [%0], {%1, %2, %3, %4};"
                 :: "l"(out), "f"(r0), "f"(r1), "f"(r2), "f"(r3) : "memory");
}

__global__ void combine_kernel(float* __restrict__ gene, const float* __restrict__ bias) {
    int idx = blockIdx.x * blockDim.x + threadIdx.x;
    if (idx >= NGENE * CH) return;
    gene[idx] += g_agg[idx] + bias[idx & 127];
}

// ---------------- launch ----------------
extern "C" void kernel_launch(void* const* d_in, const int* in_sizes, int n_in,
                              void* d_out, int out_size) {
    const float* x_gene = (const float*)d_in[0];
    const float* x_dis  = (const float*)d_in[1];
    const int* e1_src = (const int*)d_in[2];
    const int* e1_dst = (const int*)d_in[3];
    const int* e2_src = (const int*)d_in[4];
    const int* e2_dst = (const int*)d_in[5];
    const float* Wg = (const float*)d_in[6];
    const float* bg = (const float*)d_in[7];
    const float* gg = (const float*)d_in[8];
    const float* betag = (const float*)d_in[9];
    const float* Wd = (const float*)d_in[10];
    const float* bd = (const float*)d_in[11];
    const float* gd = (const float*)d_in[12];
    const float* betad = (const float*)d_in[13];
    const float* W1s = (const float*)d_in[14];
    const float* W1d = (const float*)d_in[15];
    const float* a1s = (const float*)d_in[16];
    const float* a1d = (const float*)d_in[17];
    const float* b1  = (const float*)d_in[18];
    const float* W2s = (const float*)d_in[19];
    const float* W2d = (const float*)d_in[20];
    const float* a2s = (const float*)d_in[21];
    const float* a2d = (const float*)d_in[22];
    const float* b2  = (const float*)d_in[23];

    float* out_gene = (float*)d_out;
    float* out_dis  = (float*)d_out + (size_t)NGENE * CH;

    float* xs_ptr = nullptr;
    cudaGetSymbolAddress((void**)&xs_ptr, g_xs);

    // ---- encode gene: relu(x@Wg+bg) -> BN ----
    zero_stats_kernel<<<1, 128>>>();
    sgemm_kernel<<<dim3(1, (NGENE + 127) / 128), 256>>>(x_gene, Wg, bg, out_gene,
                                                        NGENE, CH, FGENE, 3);
    colsum_kernel<<<512, 128>>>(out_gene, NGENE);
    bn_kernel<<<(NGENE * CH + 255) / 256, 256>>>(out_gene, NGENE, gg, betag);

    // ---- encode dis ----
    zero_stats_kernel<<<1, 128>>>();
    sgemm_kernel<<<dim3(1, (NDIS + 127) / 128), 256>>>(x_dis, Wd, bd, out_dis,
                                                       NDIS, CH, FDIS, 3);
    colsum_kernel<<<512, 128>>>(out_dis, NDIS);
    bn_kernel<<<(NDIS * CH + 255) / 256, 256>>>(out_dis, NDIS, gd, betad);

    // ---- relation 1: dis -> gene ----
    {
        const int E = NE, n_loop = NDIS, ET = E + n_loop;
        wld_kernel<<<2, 256>>>(W1d, a1d);
        sgemm_kernel<<<dim3(4, (NDIS + 127) / 128), 256>>>(out_dis, W1s, nullptr, xs_ptr,
                                                           NDIS, 4 * CH, CH, 0);
        ls_kernel<<<(NDIS + 7) / 8, 256>>>(a1s, NDIS);
        ld_kernel<<<(NGENE + 7) / 8, 256>>>(out_gene, NGENE);
        gat_init_kernel<<<2048, 256>>>(NGENE);
        gat_pass1_kernel<<<(ET + 255) / 256, 256>>>(e1_src, e1_dst, E, n_loop);
        gat_pass2_kernel<<<(ET + 255) / 256, 256>>>(e1_src, e1_dst, E, n_loop);
        gat_pass3_kernel<<<(ET + 7) / 8, 256>>>(e1_src, e1_dst, E, n_loop);
        combine_kernel<<<(NGENE * CH + 255) / 256, 256>>>(out_gene, b1);
    }

    // ---- relation 2: gene -> gene (updated gene) ----
    {
        const int E = NE, n_loop = NGENE, ET = E + n_loop;
        wld_kernel<<<2, 256>>>(W2d, a2d);
        sgemm_kernel<<<dim3(4, (NGENE + 127) / 128), 256>>>(out_gene, W2s, nullptr, xs_ptr,
                                                            NGENE, 4 * CH, CH, 0);
        ls_kernel<<<(NGENE + 7) / 8, 256>>>(a2s, NGENE);
        ld_kernel<<<(NGENE + 7) / 8, 256>>>(out_gene, NGENE);
        gat_init_kernel<<<2048, 256>>>(NGENE);
        gat_pass1_kernel<<<(ET + 255) / 256, 256>>>(e2_src, e2_dst, E, n_loop);
        gat_pass2_kernel<<<(ET + 255) / 256, 256>>>(e2_src, e2_dst, E, n_loop);
        gat_pass3_kernel<<<(ET + 7) / 8, 256>>>(e2_src, e2_dst, E, n_loop);
        combine_kernel<<<(NGENE * CH + 255) / 256, 256>>>(out_gene, b2);
    }
}

// round 2
// speedup vs baseline: 1.5145x; 1.5145x over previous
#include <cuda_runtime.h>
#include <math.h>

#define NGENE 50000
#define NDIS  25000
#define FGENE 512
#define FDIS  256
#define CH    128
#define NE    150000

// ---------------- scratch (static device globals; no allocation) ----------------
__device__ float  g_xs[(size_t)NGENE * 512];      // xs = x_src @ Ws  [Ns, H*C]
__device__ float  g_agg[(size_t)NGENE * CH];      // per-dst aggregation (head-mean folded)
__device__ float  g_ls[NGENE * 4];                // per-src attention logits (src part)
__device__ float  g_ld[NGENE * 4];                // per-dst attention logits (dst part)
__device__ float  g_logits[(NE + NGENE) * 4];     // per-edge logits, then p
__device__ float  g_m[NGENE * 4];                 // segment max
__device__ float  g_denom[NGENE * 4];             // segment sum
__device__ float  g_wld[512];                     // folded Wd @ a_d  [128,4]
__device__ double g_sum[CH];
__device__ double g_sumsq[CH];
__device__ float  g_scale[CH];
__device__ float  g_shift[CH];

// ---------------- helpers ----------------
__device__ __forceinline__ void atomicMaxF(float* addr, float v) {
    if (v >= 0.f) atomicMax((int*)addr, __float_as_int(v));
    else          atomicMin((unsigned int*)addr, __float_as_uint(v));
}

__device__ __forceinline__ float leaky(float x) { return x > 0.f ? x : 0.2f * x; }

// ---------------- SGEMM: C[M,N] = A[M,K] @ B[K,N] (+bias, +relu) ----------------
// 128x128 tile, BK=8, 256 threads, 8x8 per thread, double-buffered smem.
__global__ __launch_bounds__(256, 2)
void sgemm_kernel(const float* __restrict__ A, const float* __restrict__ B,
                  const float* __restrict__ bias, float* __restrict__ C,
                  int M, int N, int K, int flags)   // flags bit0=bias, bit1=relu
{
    __shared__ float As[2][8][132];
    __shared__ float Bs[2][8][132];
    const int tid = threadIdx.x;
    const int bm = blockIdx.y * 128;
    const int bn = blockIdx.x * 128;

    const int arow = tid >> 1;            // 0..127
    const int akol = (tid & 1) * 4;       // 0 or 4
    const int bkrow = tid >> 5;           // 0..7
    const int bcol = (tid & 31) * 4;      // 0..124

    const int tx = tid & 15, ty = tid >> 4;
    const int tm = ty * 8, tn = tx * 8;

    float acc[8][8];
#pragma unroll
    for (int i = 0; i < 8; i++)
#pragma unroll
        for (int j = 0; j < 8; j++) acc[i][j] = 0.f;

    const int gm = bm + arow;
    const bool arow_ok = (gm < M);
    const float* Arow = A + (size_t)gm * K;

    // prologue: load tile 0 into buffer 0
    {
        float4 av = make_float4(0.f, 0.f, 0.f, 0.f);
        if (arow_ok) av = *(const float4*)(Arow + akol);
        As[0][akol + 0][arow] = av.x;
        As[0][akol + 1][arow] = av.y;
        As[0][akol + 2][arow] = av.z;
        As[0][akol + 3][arow] = av.w;
        *(float4*)&Bs[0][bkrow][bcol] =
            *(const float4*)(B + (size_t)bkrow * N + bn + bcol);
    }
    __syncthreads();

    const int nt = K >> 3;
    int buf = 0;
    for (int t = 0; t < nt; t++) {
        float4 av2, bv2;
        const bool has = (t + 1 < nt);
        if (has) {
            const int k0 = (t + 1) << 3;
            av2 = make_float4(0.f, 0.f, 0.f, 0.f);
            if (arow_ok) av2 = *(const float4*)(Arow + k0 + akol);
            bv2 = *(const float4*)(B + (size_t)(k0 + bkrow) * N + bn + bcol);
        }
#pragma unroll
        for (int kk = 0; kk < 8; kk++) {
            float a[8], b[8];
            *(float4*)(a)     = *(const float4*)&As[buf][kk][tm];
            *(float4*)(a + 4) = *(const float4*)&As[buf][kk][tm + 4];
            *(float4*)(b)     = *(const float4*)&Bs[buf][kk][tn];
            *(float4*)(b + 4) = *(const float4*)&Bs[buf][kk][tn + 4];
#pragma unroll
            for (int i = 0; i < 8; i++)
#pragma unroll
                for (int j = 0; j < 8; j++) acc[i][j] += a[i] * b[j];
        }
        if (has) {
            const int nb = buf ^ 1;
            As[nb][akol + 0][arow] = av2.x;
            As[nb][akol + 1][arow] = av2.y;
            As[nb][akol + 2][arow] = av2.z;
            As[nb][akol + 3][arow] = av2.w;
            *(float4*)&Bs[nb][bkrow][bcol] = bv2;
        }
        __syncthreads();
        buf ^= 1;
    }

    for (int i = 0; i < 8; i++) {
        int r = bm + tm + i;
        if (r >= M) break;
        float* crow = C + (size_t)r * N + bn + tn;
#pragma unroll
        for (int j = 0; j < 8; j += 4) {
            float4 v = make_float4(acc[i][j], acc[i][j + 1], acc[i][j + 2], acc[i][j + 3]);
            if (flags & 1) {
                const float* bp = bias + bn + tn + j;
                v.x += bp[0]; v.y += bp[1]; v.z += bp[2]; v.w += bp[3];
            }
            if (flags & 2) {
                v.x = fmaxf(v.x, 0.f); v.y = fmaxf(v.y, 0.f);
                v.z = fmaxf(v.z, 0.f); v.w = fmaxf(v.w, 0.f);
            }
            *(float4*)(crow + j) = v;
        }
    }
}

// ---------------- BatchNorm ----------------
__global__ void zero_stats_kernel() {
    int c = threadIdx.x;
    g_sum[c] = 0.0; g_sumsq[c] = 0.0;
}

__global__ void colsum_kernel(const float* __restrict__ h, int M) {
    int c = threadIdx.x;   // 128
    float s = 0.f, q = 0.f;
    for (int r = blockIdx.x; r < M; r += gridDim.x) {
        float v = h[(size_t)r * CH + c];
        s += v; q += v * v;
    }
    atomicAdd(&g_sum[c], (double)s);
    atomicAdd(&g_sumsq[c], (double)q);
}

// compute per-column scale/shift ONCE (128 threads), keep apply pure-float
__global__ void bn_params_kernel(const float* __restrict__ gamma,
                                 const float* __restrict__ beta, int M) {
    int c = threadIdx.x;
    double mu = g_sum[c] / M;
    double var = g_sumsq[c] / M - mu * mu;
    float sc = gamma[c] * rsqrtf((float)var + 1e-5f);
    g_scale[c] = sc;
    g_shift[c] = beta[c] - (float)mu * sc;
}

__global__ void bn_apply_kernel(float* __restrict__ h, int M) {
    int i = blockIdx.x * blockDim.x + threadIdx.x;   // over float4s
    if (i >= M * (CH / 4)) return;
    int c = (i & 31) * 4;
    float4 v = ((float4*)h)[i];
    v.x = v.x * g_scale[c + 0] + g_shift[c + 0];
    v.y = v.y * g_scale[c + 1] + g_shift[c + 1];
    v.z = v.z * g_scale[c + 2] + g_shift[c + 2];
    v.w = v.w * g_scale[c + 3] + g_shift[c + 3];
    ((float4*)h)[i] = v;
}

// ---------------- GAT pieces ----------------
// w_ld[k][h] = sum_c Wd[k, h*128+c] * a_d[h, c]
__global__ void wld_kernel(const float* __restrict__ Wd, const float* __restrict__ ad) {
    int t = blockIdx.x * blockDim.x + threadIdx.x;
    if (t >= 512) return;
    int k = t >> 2, h = t & 3;
    float s = 0.f;
    for (int c = 0; c < 128; c++)
        s += Wd[(size_t)k * 512 + h * 128 + c] * ad[h * 128 + c];
    g_wld[k * 4 + h] = s;
}

// ls[i,h] = sum_c xs[i,h,c] * a_s[h,c]   (one warp per node)
__global__ void ls_kernel(const float* __restrict__ a_s, int N) {
    int w = (blockIdx.x * blockDim.x + threadIdx.x) >> 5;
    int lane = threadIdx.x & 31;
    if (w >= N) return;
    const float4* xr = (const float4*)g_xs + (size_t)w * 128;
    int head = lane >> 3, sub = lane & 7;
    const float4* ar = (const float4*)a_s + head * 32;
    float acc = 0.f;
#pragma unroll
    for (int j = 0; j < 4; j++) {
        float4 x = xr[lane * 4 + j];
        float4 a = ar[sub * 4 + j];
        acc += x.x * a.x + x.y * a.y + x.z * a.z + x.w * a.w;
    }
    acc += __shfl_xor_sync(0xffffffffu, acc, 4);
    acc += __shfl_xor_sync(0xffffffffu, acc, 2);
    acc += __shfl_xor_sync(0xffffffffu, acc, 1);
    if (sub == 0) g_ls[w * 4 + head] = acc;
}

// ld[i,h] = x_dst[i] @ w_ld[:,h]   (one warp per node)
__global__ void ld_kernel(const float* __restrict__ x, int N) {
    int w = (blockIdx.x * blockDim.x + threadIdx.x) >> 5;
    int lane = threadIdx.x & 31;
    if (w >= N) return;
    const float* row = x + (size_t)w * CH;
    float h0 = 0.f, h1 = 0.f, h2 = 0.f, h3 = 0.f;
#pragma unroll
    for (int j = 0; j < 4; j++) {
        int k = lane + 32 * j;
        float v = row[k];
        float4 wv = ((const float4*)g_wld)[k];
        h0 += v * wv.x; h1 += v * wv.y; h2 += v * wv.z; h3 += v * wv.w;
    }
#pragma unroll
    for (int off = 16; off > 0; off >>= 1) {
        h0 += __shfl_xor_sync(0xffffffffu, h0, off);
        h1 += __shfl_xor_sync(0xffffffffu, h1, off);
        h2 += __shfl_xor_sync(0xffffffffu, h2, off);
        h3 += __shfl_xor_sync(0xffffffffu, h3, off);
    }
    if (lane == 0) ((float4*)g_ld)[w] = make_float4(h0, h1, h2, h3);
}

__global__ void gat_init_kernel(int n_dst) {
    int stride = gridDim.x * blockDim.x;
    int start = blockIdx.x * blockDim.x + threadIdx.x;
    float ninf = __int_as_float(0xff800000);
    for (int i = start; i < n_dst * CH; i += stride) g_agg[i] = 0.f;
    for (int i = start; i < n_dst * 4; i += stride) { g_m[i] = ninf; g_denom[i] = 0.f; }
}

// pass1: logits + segment max
__global__ void gat_pass1_kernel(const int* __restrict__ src, const int* __restrict__ dst,
                                 int E, int n_loop) {
    int e = blockIdx.x * blockDim.x + threadIdx.x;
    if (e >= E + n_loop) return;
    int s, d; bool mask;
    if (e < E) { s = src[e]; d = dst[e]; mask = (s != d); }
    else       { s = d = e - E; mask = true; }
    float4 a = ((const float4*)g_ls)[s];
    float4 b = ((const float4*)g_ld)[d];
    float l0 = leaky(a.x + b.x), l1 = leaky(a.y + b.y);
    float l2 = leaky(a.z + b.z), l3 = leaky(a.w + b.w);
    if (!mask) { l0 = l1 = l2 = l3 = -1e30f; }
    ((float4*)g_logits)[e] = make_float4(l0, l1, l2, l3);
    atomicMaxF(&g_m[d * 4 + 0], l0);
    atomicMaxF(&g_m[d * 4 + 1], l1);
    atomicMaxF(&g_m[d * 4 + 2], l2);
    atomicMaxF(&g_m[d * 4 + 3], l3);
}

// pass2: p = exp(logit - m[dst]) * mask ; segment sum
__global__ void gat_pass2_kernel(const int* __restrict__ src, const int* __restrict__ dst,
                                 int E, int n_loop) {
    int e = blockIdx.x * blockDim.x + threadIdx.x;
    if (e >= E + n_loop) return;
    int d; bool mask;
    if (e < E) { int s = src[e]; d = dst[e]; mask = (s != d); }
    else       { d = e - E; mask = true; }
    float4 L = ((const float4*)g_logits)[e];
    float4 M4 = ((const float4*)g_m)[d];
    float p0 = mask ? expf(L.x - M4.x) : 0.f;
    float p1 = mask ? expf(L.y - M4.y) : 0.f;
    float p2 = mask ? expf(L.z - M4.z) : 0.f;
    float p3 = mask ? expf(L.w - M4.w) : 0.f;
    ((float4*)g_logits)[e] = make_float4(p0, p1, p2, p3);
    atomicAdd(&g_denom[d * 4 + 0], p0);
    atomicAdd(&g_denom[d * 4 + 1], p1);
    atomicAdd(&g_denom[d * 4 + 2], p2);
    atomicAdd(&g_denom[d * 4 + 3], p3);
}

// pass3: agg[dst] += (1/4) * sum_h alpha_h * xs[src,h,:]   (one warp per edge)
__global__ void gat_pass3_kernel(const int* __restrict__ src, const int* __restrict__ dst,
                                 int E, int n_loop) {
    int w = (blockIdx.x * blockDim.x + threadIdx.x) >> 5;
    int lane = threadIdx.x & 31;
    if (w >= E + n_loop) return;
    int s, d;
    if (w < E) { s = src[w]; d = dst[w]; }
    else       { s = d = w - E; }
    float4 P = ((const float4*)g_logits)[w];
    float4 D = ((const float4*)g_denom)[d];
    float a0 = 0.25f * P.x / (D.x > 0.f ? D.x : 1.f);
    float a1 = 0.25f * P.y / (D.y > 0.f ? D.y : 1.f);
    float a2 = 0.25f * P.z / (D.z > 0.f ? D.z : 1.f);
    float a3 = 0.25f * P.w / (D.w > 0.f ? D.w : 1.f);
    const float4* xr = (const float4*)g_xs + (size_t)s * 128;
    float4 x0 = xr[lane], x1 = xr[32 + lane], x2 = xr[64 + lane], x3 = xr[96 + lane];
    float r0 = a0 * x0.x + a1 * x1.x + a2 * x2.x + a3 * x3.x;
    float r1 = a0 * x0.y + a1 * x1.y + a2 * x2.y + a3 * x3.y;
    float r2 = a0 * x0.z + a1 * x1.z + a2 * x2.z + a3 * x3.z;
    float r3 = a0 * x0.w + a1 * x1.w + a2 * x2.w + a3 * x3.w;
    float* out = g_agg + (size_t)d * CH + lane * 4;
    asm volatile("red.global.add.v4.f32 [%0], {%1, %2, %3, %4};"
                 :: "l"(out), "f"(r0), "f"(r1), "f"(r2), "f"(r3) : "memory");
}

__global__ void combine_kernel(float* __restrict__ gene, const float* __restrict__ bias) {
    int idx = blockIdx.x * blockDim.x + threadIdx.x;
    if (idx >= NGENE * CH) return;
    gene[idx] += g_agg[idx] + bias[idx & 127];
}

// ---------------- launch ----------------
extern "C" void kernel_launch(void* const* d_in, const int* in_sizes, int n_in,
                              void* d_out, int out_size) {
    const float* x_gene = (const float*)d_in[0];
    const float* x_dis  = (const float*)d_in[1];
    const int* e1_src = (const int*)d_in[2];
    const int* e1_dst = (const int*)d_in[3];
    const int* e2_src = (const int*)d_in[4];
    const int* e2_dst = (const int*)d_in[5];
    const float* Wg = (const float*)d_in[6];
    const float* bg = (const float*)d_in[7];
    const float* gg = (const float*)d_in[8];
    const float* betag = (const float*)d_in[9];
    const float* Wd = (const float*)d_in[10];
    const float* bd = (const float*)d_in[11];
    const float* gd = (const float*)d_in[12];
    const float* betad = (const float*)d_in[13];
    const float* W1s = (const float*)d_in[14];
    const float* W1d = (const float*)d_in[15];
    const float* a1s = (const float*)d_in[16];
    const float* a1d = (const float*)d_in[17];
    const float* b1  = (const float*)d_in[18];
    const float* W2s = (const float*)d_in[19];
    const float* W2d = (const float*)d_in[20];
    const float* a2s = (const float*)d_in[21];
    const float* a2d = (const float*)d_in[22];
    const float* b2  = (const float*)d_in[23];

    float* out_gene = (float*)d_out;
    float* out_dis  = (float*)d_out + (size_t)NGENE * CH;

    float* xs_ptr = nullptr;
    cudaGetSymbolAddress((void**)&xs_ptr, g_xs);

    // ---- encode gene: relu(x@Wg+bg) -> BN ----
    zero_stats_kernel<<<1, 128>>>();
    sgemm_kernel<<<dim3(1, (NGENE + 127) / 128), 256>>>(x_gene, Wg, bg, out_gene,
                                                        NGENE, CH, FGENE, 3);
    colsum_kernel<<<512, 128>>>(out_gene, NGENE);
    bn_params_kernel<<<1, 128>>>(gg, betag, NGENE);
    bn_apply_kernel<<<(NGENE * 32 + 255) / 256, 256>>>(out_gene, NGENE);

    // ---- encode dis ----
    zero_stats_kernel<<<1, 128>>>();
    sgemm_kernel<<<dim3(1, (NDIS + 127) / 128), 256>>>(x_dis, Wd, bd, out_dis,
                                                       NDIS, CH, FDIS, 3);
    colsum_kernel<<<512, 128>>>(out_dis, NDIS);
    bn_params_kernel<<<1, 128>>>(gd, betad, NDIS);
    bn_apply_kernel<<<(NDIS * 32 + 255) / 256, 256>>>(out_dis, NDIS);

    // ---- relation 1: dis -> gene ----
    {
        const int E = NE, n_loop = NDIS, ET = E + n_loop;
        wld_kernel<<<2, 256>>>(W1d, a1d);
        sgemm_kernel<<<dim3(4, (NDIS + 127) / 128), 256>>>(out_dis, W1s, nullptr, xs_ptr,
                                                           NDIS, 4 * CH, CH, 0);
        ls_kernel<<<(NDIS + 7) / 8, 256>>>(a1s, NDIS);
        ld_kernel<<<(NGENE + 7) / 8, 256>>>(out_gene, NGENE);
        gat_init_kernel<<<2048, 256>>>(NGENE);
        gat_pass1_kernel<<<(ET + 255) / 256, 256>>>(e1_src, e1_dst, E, n_loop);
        gat_pass2_kernel<<<(ET + 255) / 256, 256>>>(e1_src, e1_dst, E, n_loop);
        gat_pass3_kernel<<<(ET + 7) / 8, 256>>>(e1_src, e1_dst, E, n_loop);
        combine_kernel<<<(NGENE * CH + 255) / 256, 256>>>(out_gene, b1);
    }

    // ---- relation 2: gene -> gene (updated gene) ----
    {
        const int E = NE, n_loop = NGENE, ET = E + n_loop;
        wld_kernel<<<2, 256>>>(W2d, a2d);
        sgemm_kernel<<<dim3(4, (NGENE + 127) / 128), 256>>>(out_gene, W2s, nullptr, xs_ptr,
                                                            NGENE, 4 * CH, CH, 0);
        ls_kernel<<<(NGENE + 7) / 8, 256>>>(a2s, NGENE);
        ld_kernel<<<(NGENE + 7) / 8, 256>>>(out_gene, NGENE);
        gat_init_kernel<<<2048, 256>>>(NGENE);
        gat_pass1_kernel<<<(ET + 255) / 256, 256>>>(e2_src, e2_dst, E, n_loop);
        gat_pass2_kernel<<<(ET + 255) / 256, 256>>>(e2_src, e2_dst, E, n_loop);
        gat_pass3_kernel<<<(ET + 7) / 8, 256>>>(e2_src, e2_dst, E, n_loop);
        combine_kernel<<<(NGENE * CH + 255) / 256, 256>>>(out_gene, b2);
    }
}

// round 4
// speedup vs baseline: 2.0442x; 1.3497x over previous
#include <cuda_runtime.h>
#include <cuda_bf16.h>
#include <math.h>
#include <cstdint>

#define NGENE 50000
#define NDIS  25000
#define FGENE 512
#define FDIS  256
#define CH    128
#define NE    150000

// ---------------- scratch (static device globals; no allocation) ----------------
__device__ float  g_xs[(size_t)NGENE * 512];      // xs = x_src @ Ws  [Ns, H*C]
__device__ float  g_agg[(size_t)NGENE * CH];      // per-dst aggregation
__device__ float  g_ls[NGENE * 4];
__device__ float  g_ld[NGENE * 4];
__device__ float  g_logits[(NE + NGENE) * 4];
__device__ float  g_m[NGENE * 4];
__device__ float  g_denom[NGENE * 4];
__device__ float  g_wld[512];
__device__ double g_sum[CH];
__device__ double g_sumsq[CH];
__device__ float  g_scale[CH];
__device__ float  g_shift[CH];
// split-bf16 GEMM operands
__device__ __nv_bfloat16 g_ahi[(size_t)NGENE * 512];
__device__ __nv_bfloat16 g_alo[(size_t)NGENE * 512];
__device__ __nv_bfloat16 g_bthi[512 * 128];
__device__ __nv_bfloat16 g_btlo[512 * 128];

// ---------------- split conversions ----------------
__global__ void split_a_kernel(const float* __restrict__ A,
                               __nv_bfloat16* __restrict__ hi,
                               __nv_bfloat16* __restrict__ lo, int n4) {
    int i = blockIdx.x * blockDim.x + threadIdx.x;
    if (i >= n4) return;
    float4 v = ((const float4*)A)[i];
    __nv_bfloat16 h0 = __float2bfloat16(v.x), h1 = __float2bfloat16(v.y);
    __nv_bfloat16 h2 = __float2bfloat16(v.z), h3 = __float2bfloat16(v.w);
    __nv_bfloat16 l0 = __float2bfloat16(v.x - __bfloat162float(h0));
    __nv_bfloat16 l1 = __float2bfloat16(v.y - __bfloat162float(h1));
    __nv_bfloat16 l2 = __float2bfloat16(v.z - __bfloat162float(h2));
    __nv_bfloat16 l3 = __float2bfloat16(v.w - __bfloat162float(h3));
    ((__nv_bfloat162*)hi)[2 * i]     = __nv_bfloat162(h0, h1);
    ((__nv_bfloat162*)hi)[2 * i + 1] = __nv_bfloat162(h2, h3);
    ((__nv_bfloat162*)lo)[2 * i]     = __nv_bfloat162(l0, l1);
    ((__nv_bfloat162*)lo)[2 * i + 1] = __nv_bfloat162(l2, l3);
}

// B [K,N] fp32 -> Bt hi/lo [N,K] bf16 (transpose; tiny)
__global__ void split_bt_kernel(const float* __restrict__ B,
                                __nv_bfloat16* __restrict__ thi,
                                __nv_bfloat16* __restrict__ tlo, int K, int N) {
    int idx = blockIdx.x * blockDim.x + threadIdx.x;
    if (idx >= K * N) return;
    int k = idx / N, n = idx % N;
    float v = B[idx];
    __nv_bfloat16 h = __float2bfloat16(v);
    thi[(size_t)n * K + k] = h;
    tlo[(size_t)n * K + k] = __float2bfloat16(v - __bfloat162float(h));
}

// ---------------- split-bf16 GEMM via mma.sync (HMMA) ----------------
// C[M,N] = A[M,K] @ B[K,N]; A as hi/lo [M,K] bf16, B as Bt hi/lo [N,K] bf16.
// CTA tile 128x128, BK=32, 8 warps (4 x 2), each warp 32(M) x 64(N).
#define SST 40   // smem row stride in bf16 elements (conflict-free: r*20 mod 32 distinct)

__device__ __forceinline__ void mma16816(float* c, const uint32_t* a,
                                         uint32_t b0, uint32_t b1) {
    asm volatile("mma.sync.aligned.m16n8k16.row.col.f32.bf16.bf16.f32 "
                 "{%0,%1,%2,%3}, {%4,%5,%6,%7}, {%8,%9}, {%0,%1,%2,%3};"
                 : "+f"(c[0]), "+f"(c[1]), "+f"(c[2]), "+f"(c[3])
                 : "r"(a[0]), "r"(a[1]), "r"(a[2]), "r"(a[3]), "r"(b0), "r"(b1));
}

__global__ __launch_bounds__(256, 2)
void gemm_mma_kernel(const __nv_bfloat16* __restrict__ Ahi, const __nv_bfloat16* __restrict__ Alo,
                     const __nv_bfloat16* __restrict__ Bthi, const __nv_bfloat16* __restrict__ Btlo,
                     const float* __restrict__ bias, float* __restrict__ C,
                     int M, int N, int K, int flags)   // flags bit0=bias, bit1=relu
{
    __shared__ __nv_bfloat16 sAh[128 * SST];
    __shared__ __nv_bfloat16 sAl[128 * SST];
    __shared__ __nv_bfloat16 sBh[128 * SST];
    __shared__ __nv_bfloat16 sBl[128 * SST];

    const int tid = threadIdx.x, wid = tid >> 5, lane = tid & 31;
    const int bm = blockIdx.y * 128, bn = blockIdx.x * 128;
    const int wm = (wid & 3) * 32, wn = (wid >> 2) * 64;
    const int lr = lane >> 2, lc = (lane & 3) * 2;

    float acc[2][8][4];
#pragma unroll
    for (int mt = 0; mt < 2; mt++)
#pragma unroll
        for (int nt = 0; nt < 8; nt++)
#pragma unroll
            for (int j = 0; j < 4; j++) acc[mt][nt][j] = 0.f;

    for (int k0 = 0; k0 < K; k0 += 32) {
        // fill 4 tiles of 128 x 32 bf16
#pragma unroll
        for (int i0 = 0; i0 < 512; i0 += 256) {
            const int i = i0 + tid;
            const int r = i >> 2, c8 = (i & 3) * 8;
            const int so = r * SST + c8;
            const int gr = bm + r;
            uint4 vh = make_uint4(0, 0, 0, 0), vl = make_uint4(0, 0, 0, 0);
            if (gr < M) {
                const size_t goff = (size_t)gr * K + k0 + c8;
                vh = *(const uint4*)(Ahi + goff);
                vl = *(const uint4*)(Alo + goff);
            }
            *(uint2*)(sAh + so)     = make_uint2(vh.x, vh.y);
            *(uint2*)(sAh + so + 4) = make_uint2(vh.z, vh.w);
            *(uint2*)(sAl + so)     = make_uint2(vl.x, vl.y);
            *(uint2*)(sAl + so + 4) = make_uint2(vl.z, vl.w);
            const size_t boff = (size_t)(bn + r) * K + k0 + c8;
            uint4 wh = *(const uint4*)(Bthi + boff);
            uint4 wl = *(const uint4*)(Btlo + boff);
            *(uint2*)(sBh + so)     = make_uint2(wh.x, wh.y);
            *(uint2*)(sBh + so + 4) = make_uint2(wh.z, wh.w);
            *(uint2*)(sBl + so)     = make_uint2(wl.x, wl.y);
            *(uint2*)(sBl + so + 4) = make_uint2(wl.z, wl.w);
        }
        __syncthreads();

#pragma unroll
        for (int ks = 0; ks < 2; ks++) {
            const int kb = ks * 16;
            uint32_t ah[2][4], al[2][4];
#pragma unroll
            for (int mt = 0; mt < 2; mt++) {
                const int rb = wm + mt * 16 + lr;
                ah[mt][0] = *(const uint32_t*)(sAh + (rb)     * SST + kb + lc);
                ah[mt][1] = *(const uint32_t*)(sAh + (rb + 8) * SST + kb + lc);
                ah[mt][2] = *(const uint32_t*)(sAh + (rb)     * SST + kb + 8 + lc);
                ah[mt][3] = *(const uint32_t*)(sAh + (rb + 8) * SST + kb + 8 + lc);
                al[mt][0] = *(const uint32_t*)(sAl + (rb)     * SST + kb + lc);
                al[mt][1] = *(const uint32_t*)(sAl + (rb + 8) * SST + kb + lc);
                al[mt][2] = *(const uint32_t*)(sAl + (rb)     * SST + kb + 8 + lc);
                al[mt][3] = *(const uint32_t*)(sAl + (rb + 8) * SST + kb + 8 + lc);
            }
#pragma unroll
            for (int nt = 0; nt < 8; nt++) {
                const int nrow = wn + nt * 8 + lr;
                const uint32_t bh0 = *(const uint32_t*)(sBh + nrow * SST + kb + lc);
                const uint32_t bh1 = *(const uint32_t*)(sBh + nrow * SST + kb + 8 + lc);
                const uint32_t bl0 = *(const uint32_t*)(sBl + nrow * SST + kb + lc);
                const uint32_t bl1 = *(const uint32_t*)(sBl + nrow * SST + kb + 8 + lc);
#pragma unroll
                for (int mt = 0; mt < 2; mt++) {
                    mma16816(acc[mt][nt], ah[mt], bh0, bh1);
                    mma16816(acc[mt][nt], ah[mt], bl0, bl1);
                    mma16816(acc[mt][nt], al[mt], bh0, bh1);
                }
            }
        }
        __syncthreads();
    }

    // epilogue
#pragma unroll
    for (int mt = 0; mt < 2; mt++) {
        const int r0 = bm + wm + mt * 16 + lr;
#pragma unroll
        for (int nt = 0; nt < 8; nt++) {
            const int col = bn + wn + nt * 8 + lc;
            float2 v0 = make_float2(acc[mt][nt][0], acc[mt][nt][1]);
            float2 v1 = make_float2(acc[mt][nt][2], acc[mt][nt][3]);
            if (flags & 1) {
                float2 bb = *(const float2*)(bias + col);
                v0.x += bb.x; v0.y += bb.y; v1.x += bb.x; v1.y += bb.y;
            }
            if (flags & 2) {
                v0.x = fmaxf(v0.x, 0.f); v0.y = fmaxf(v0.y, 0.f);
                v1.x = fmaxf(v1.x, 0.f); v1.y = fmaxf(v1.y, 0.f);
            }
            if (r0 < M)     *(float2*)(C + (size_t)r0 * N + col) = v0;
            if (r0 + 8 < M) *(float2*)(C + (size_t)(r0 + 8) * N + col) = v1;
        }
    }
}

// ---------------- helpers ----------------
__device__ __forceinline__ void atomicMaxF(float* addr, float v) {
    if (v >= 0.f) atomicMax((int*)addr, __float_as_int(v));
    else          atomicMin((unsigned int*)addr, __float_as_uint(v));
}
__device__ __forceinline__ float leaky(float x) { return x > 0.f ? x : 0.2f * x; }

// ---------------- BatchNorm ----------------
__global__ void zero_stats_kernel() {
    int c = threadIdx.x;
    g_sum[c] = 0.0; g_sumsq[c] = 0.0;
}

__global__ void colsum_kernel(const float* __restrict__ h, int M) {
    int c = threadIdx.x;
    float s = 0.f, q = 0.f;
    for (int r = blockIdx.x; r < M; r += gridDim.x) {
        float v = h[(size_t)r * CH + c];
        s += v; q += v * v;
    }
    atomicAdd(&g_sum[c], (double)s);
    atomicAdd(&g_sumsq[c], (double)q);
}

__global__ void bn_params_kernel(const float* __restrict__ gamma,
                                 const float* __restrict__ beta, int M) {
    int c = threadIdx.x;
    double mu = g_sum[c] / M;
    double var = g_sumsq[c] / M - mu * mu;
    float sc = gamma[c] * rsqrtf((float)var + 1e-5f);
    g_scale[c] = sc;
    g_shift[c] = beta[c] - (float)mu * sc;
}

__global__ void bn_apply_kernel(float* __restrict__ h, int M) {
    int i = blockIdx.x * blockDim.x + threadIdx.x;
    if (i >= M * (CH / 4)) return;
    int c = (i & 31) * 4;
    float4 v = ((float4*)h)[i];
    v.x = v.x * g_scale[c + 0] + g_shift[c + 0];
    v.y = v.y * g_scale[c + 1] + g_shift[c + 1];
    v.z = v.z * g_scale[c + 2] + g_shift[c + 2];
    v.w = v.w * g_scale[c + 3] + g_shift[c + 3];
    ((float4*)h)[i] = v;
}

// ---------------- GAT pieces ----------------
__global__ void wld_kernel(const float* __restrict__ Wd, const float* __restrict__ ad) {
    int t = blockIdx.x * blockDim.x + threadIdx.x;
    if (t >= 512) return;
    int k = t >> 2, h = t & 3;
    float s = 0.f;
    for (int c = 0; c < 128; c++)
        s += Wd[(size_t)k * 512 + h * 128 + c] * ad[h * 128 + c];
    g_wld[k * 4 + h] = s;
}

__global__ void ls_kernel(const float* __restrict__ a_s, int N) {
    int w = (blockIdx.x * blockDim.x + threadIdx.x) >> 5;
    int lane = threadIdx.x & 31;
    if (w >= N) return;
    const float4* xr = (const float4*)g_xs + (size_t)w * 128;
    int head = lane >> 3, sub = lane & 7;
    const float4* ar = (const float4*)a_s + head * 32;
    float acc = 0.f;
#pragma unroll
    for (int j = 0; j < 4; j++) {
        float4 x = xr[lane * 4 + j];
        float4 a = ar[sub * 4 + j];
        acc += x.x * a.x + x.y * a.y + x.z * a.z + x.w * a.w;
    }
    acc += __shfl_xor_sync(0xffffffffu, acc, 4);
    acc += __shfl_xor_sync(0xffffffffu, acc, 2);
    acc += __shfl_xor_sync(0xffffffffu, acc, 1);
    if (sub == 0) g_ls[w * 4 + head] = acc;
}

__global__ void ld_kernel(const float* __restrict__ x, int N) {
    int w = (blockIdx.x * blockDim.x + threadIdx.x) >> 5;
    int lane = threadIdx.x & 31;
    if (w >= N) return;
    const float* row = x + (size_t)w * CH;
    float h0 = 0.f, h1 = 0.f, h2 = 0.f, h3 = 0.f;
#pragma unroll
    for (int j = 0; j < 4; j++) {
        int k = lane + 32 * j;
        float v = row[k];
        float4 wv = ((const float4*)g_wld)[k];
        h0 += v * wv.x; h1 += v * wv.y; h2 += v * wv.z; h3 += v * wv.w;
    }
#pragma unroll
    for (int off = 16; off > 0; off >>= 1) {
        h0 += __shfl_xor_sync(0xffffffffu, h0, off);
        h1 += __shfl_xor_sync(0xffffffffu, h1, off);
        h2 += __shfl_xor_sync(0xffffffffu, h2, off);
        h3 += __shfl_xor_sync(0xffffffffu, h3, off);
    }
    if (lane == 0) ((float4*)g_ld)[w] = make_float4(h0, h1, h2, h3);
}

__global__ void gat_init_kernel(int n_dst) {
    int stride = gridDim.x * blockDim.x;
    int start = blockIdx.x * blockDim.x + threadIdx.x;
    float ninf = __int_as_float(0xff800000);
    for (int i = start; i < n_dst * CH; i += stride) g_agg[i] = 0.f;
    for (int i = start; i < n_dst * 4; i += stride) { g_m[i] = ninf; g_denom[i] = 0.f; }
}

__global__ void gat_pass1_kernel(const int* __restrict__ src, const int* __restrict__ dst,
                                 int E, int n_loop) {
    int e = blockIdx.x * blockDim.x + threadIdx.x;
    if (e >= E + n_loop) return;
    int s, d; bool mask;
    if (e < E) { s = src[e]; d = dst[e]; mask = (s != d); }
    else       { s = d = e - E; mask = true; }
    float4 a = ((const float4*)g_ls)[s];
    float4 b = ((const float4*)g_ld)[d];
    float l0 = leaky(a.x + b.x), l1 = leaky(a.y + b.y);
    float l2 = leaky(a.z + b.z), l3 = leaky(a.w + b.w);
    if (!mask) { l0 = l1 = l2 = l3 = -1e30f; }
    ((float4*)g_logits)[e] = make_float4(l0, l1, l2, l3);
    atomicMaxF(&g_m[d * 4 + 0], l0);
    atomicMaxF(&g_m[d * 4 + 1], l1);
    atomicMaxF(&g_m[d * 4 + 2], l2);
    atomicMaxF(&g_m[d * 4 + 3], l3);
}

__global__ void gat_pass2_kernel(const int* __restrict__ src, const int* __restrict__ dst,
                                 int E, int n_loop) {
    int e = blockIdx.x * blockDim.x + threadIdx.x;
    if (e >= E + n_loop) return;
    int d; bool mask;
    if (e < E) { int s = src[e]; d = dst[e]; mask = (s != d); }
    else       { d = e - E; mask = true; }
    float4 L = ((const float4*)g_logits)[e];
    float4 M4 = ((const float4*)g_m)[d];
    float p0 = mask ? expf(L.x - M4.x) : 0.f;
    float p1 = mask ? expf(L.y - M4.y) : 0.f;
    float p2 = mask ? expf(L.z - M4.z) : 0.f;
    float p3 = mask ? expf(L.w - M4.w) : 0.f;
    ((float4*)g_logits)[e] = make_float4(p0, p1, p2, p3);
    atomicAdd(&g_denom[d * 4 + 0], p0);
    atomicAdd(&g_denom[d * 4 + 1], p1);
    atomicAdd(&g_denom[d * 4 + 2], p2);
    atomicAdd(&g_denom[d * 4 + 3], p3);
}

__global__ void gat_pass3_kernel(const int* __restrict__ src, const int* __restrict__ dst,
                                 int E, int n_loop) {
    int w = (blockIdx.x * blockDim.x + threadIdx.x) >> 5;
    int lane = threadIdx.x & 31;
    if (w >= E + n_loop) return;
    int s, d;
    if (w < E) { s = src[w]; d = dst[w]; }
    else       { s = d = w - E; }
    float4 P = ((const float4*)g_logits)[w];
    float4 D = ((const float4*)g_denom)[d];
    float a0 = 0.25f * P.x / (D.x > 0.f ? D.x : 1.f);
    float a1 = 0.25f * P.y / (D.y > 0.f ? D.y : 1.f);
    float a2 = 0.25f * P.z / (D.z > 0.f ? D.z : 1.f);
    float a3 = 0.25f * P.w / (D.w > 0.f ? D.w : 1.f);
    const float4* xr = (const float4*)g_xs + (size_t)s * 128;
    float4 x0 = xr[lane], x1 = xr[32 + lane], x2 = xr[64 + lane], x3 = xr[96 + lane];
    float r0 = a0 * x0.x + a1 * x1.x + a2 * x2.x + a3 * x3.x;
    float r1 = a0 * x0.y + a1 * x1.y + a2 * x2.y + a3 * x3.y;
    float r2 = a0 * x0.z + a1 * x1.z + a2 * x2.z + a3 * x3.z;
    float r3 = a0 * x0.w + a1 * x1.w + a2 * x2.w + a3 * x3.w;
    float* out = g_agg + (size_t)d * CH + lane * 4;
    asm volatile("red.global.add.v4.f32 [%0], {%1, %2, %3, %4};"
                 :: "l"(out), "f"(r0), "f"(r1), "f"(r2), "f"(r3) : "memory");
}

__global__ void combine_kernel(float* __restrict__ gene, const float* __restrict__ bias) {
    int idx = blockIdx.x * blockDim.x + threadIdx.x;
    if (idx >= NGENE * CH) return;
    gene[idx] += g_agg[idx] + bias[idx & 127];
}

// ---------------- launch ----------------
extern "C" void kernel_launch(void* const* d_in, const int* in_sizes, int n_in,
                              void* d_out, int out_size) {
    const float* x_gene = (const float*)d_in[0];
    const float* x_dis  = (const float*)d_in[1];
    const int* e1_src = (const int*)d_in[2];
    const int* e1_dst = (const int*)d_in[3];
    const int* e2_src = (const int*)d_in[4];
    const int* e2_dst = (const int*)d_in[5];
    const float* Wg = (const float*)d_in[6];
    const float* bg = (const float*)d_in[7];
    const float* gg = (const float*)d_in[8];
    const float* betag = (const float*)d_in[9];
    const float* Wd = (const float*)d_in[10];
    const float* bd = (const float*)d_in[11];
    const float* gd = (const float*)d_in[12];
    const float* betad = (const float*)d_in[13];
    const float* W1s = (const float*)d_in[14];
    const float* W1d = (const float*)d_in[15];
    const float* a1s = (const float*)d_in[16];
    const float* a1d = (const float*)d_in[17];
    const float* b1  = (const float*)d_in[18];
    const float* W2s = (const float*)d_in[19];
    const float* W2d = (const float*)d_in[20];
    const float* a2s = (const float*)d_in[21];
    const float* a2d = (const float*)d_in[22];
    const float* b2  = (const float*)d_in[23];

    float* out_gene = (float*)d_out;
    float* out_dis  = (float*)d_out + (size_t)NGENE * CH;

    float* xs_ptr = nullptr;
    cudaGetSymbolAddress((void**)&xs_ptr, g_xs);
    __nv_bfloat16 *ahi, *alo, *bthi, *btlo;
    cudaGetSymbolAddress((void**)&ahi, g_ahi);
    cudaGetSymbolAddress((void**)&alo, g_alo);
    cudaGetSymbolAddress((void**)&bthi, g_bthi);
    cudaGetSymbolAddress((void**)&btlo, g_btlo);

    // ---- encode gene: relu(x@Wg+bg) -> BN ----
    zero_stats_kernel<<<1, 128>>>();
    split_a_kernel<<<(NGENE * FGENE / 4 + 255) / 256, 256>>>(x_gene, ahi, alo, NGENE * FGENE / 4);
    split_bt_kernel<<<(FGENE * CH + 255) / 256, 256>>>(Wg, bthi, btlo, FGENE, CH);
    gemm_mma_kernel<<<dim3(1, (NGENE + 127) / 128), 256>>>(
        ahi, alo, bthi, btlo, bg, out_gene, NGENE, CH, FGENE, 3);
    colsum_kernel<<<512, 128>>>(out_gene, NGENE);
    bn_params_kernel<<<1, 128>>>(gg, betag, NGENE);
    bn_apply_kernel<<<(NGENE * 32 + 255) / 256, 256>>>(out_gene, NGENE);

    // ---- encode dis ----
    zero_stats_kernel<<<1, 128>>>();
    split_a_kernel<<<(NDIS * FDIS / 4 + 255) / 256, 256>>>(x_dis, ahi, alo, NDIS * FDIS / 4);
    split_bt_kernel<<<(FDIS * CH + 255) / 256, 256>>>(Wd, bthi, btlo, FDIS, CH);
    gemm_mma_kernel<<<dim3(1, (NDIS + 127) / 128), 256>>>(
        ahi, alo, bthi, btlo, bd, out_dis, NDIS, CH, FDIS, 3);
    colsum_kernel<<<512, 128>>>(out_dis, NDIS);
    bn_params_kernel<<<1, 128>>>(gd, betad, NDIS);
    bn_apply_kernel<<<(NDIS * 32 + 255) / 256, 256>>>(out_dis, NDIS);

    // ---- relation 1: dis -> gene ----
    {
        const int E = NE, n_loop = NDIS, ET = E + n_loop;
        wld_kernel<<<2, 256>>>(W1d, a1d);
        split_a_kernel<<<(NDIS * CH / 4 + 255) / 256, 256>>>(out_dis, ahi, alo, NDIS * CH / 4);
        split_bt_kernel<<<(CH * 512 + 255) / 256, 256>>>(W1s, bthi, btlo, CH, 512);
        gemm_mma_kernel<<<dim3(4, (NDIS + 127) / 128), 256>>>(
            ahi, alo, bthi, btlo, nullptr, xs_ptr, NDIS, 512, CH, 0);
        ls_kernel<<<(NDIS + 7) / 8, 256>>>(a1s, NDIS);
        ld_kernel<<<(NGENE + 7) / 8, 256>>>(out_gene, NGENE);
        gat_init_kernel<<<2048, 256>>>(NGENE);
        gat_pass1_kernel<<<(ET + 255) / 256, 256>>>(e1_src, e1_dst, E, n_loop);
        gat_pass2_kernel<<<(ET + 255) / 256, 256>>>(e1_src, e1_dst, E, n_loop);
        gat_pass3_kernel<<<(ET + 7) / 8, 256>>>(e1_src, e1_dst, E, n_loop);
        combine_kernel<<<(NGENE * CH + 255) / 256, 256>>>(out_gene, b1);
    }

    // ---- relation 2: gene -> gene (updated gene) ----
    {
        const int E = NE, n_loop = NGENE, ET = E + n_loop;
        wld_kernel<<<2, 256>>>(W2d, a2d);
        split_a_kernel<<<(NGENE * CH / 4 + 255) / 256, 256>>>(out_gene, ahi, alo, NGENE * CH / 4);
        split_bt_kernel<<<(CH * 512 + 255) / 256, 256>>>(W2s, bthi, btlo, CH, 512);
        gemm_mma_kernel<<<dim3(4, (NGENE + 127) / 128), 256>>>(
            ahi, alo, bthi, btlo, nullptr, xs_ptr, NGENE, 512, CH, 0);
        ls_kernel<<<(NGENE + 7) / 8, 256>>>(a2s, NGENE);
        ld_kernel<<<(NGENE + 7) / 8, 256>>>(out_gene, NGENE);
        gat_init_kernel<<<2048, 256>>>(NGENE);
        gat_pass1_kernel<<<(ET + 255) / 256, 256>>>(e2_src, e2_dst, E, n_loop);
        gat_pass2_kernel<<<(ET + 255) / 256, 256>>>(e2_src, e2_dst, E, n_loop);
        gat_pass3_kernel<<<(ET + 7) / 8, 256>>>(e2_src, e2_dst, E, n_loop);
        combine_kernel<<<(NGENE * CH + 255) / 256, 256>>>(out_gene, b2);
    }
}

// round 5
// speedup vs baseline: 2.4293x; 1.1884x over previous
#include <cuda_runtime.h>
#include <cuda_bf16.h>
#include <math.h>
#include <cstdint>

#define NGENE 50000
#define NDIS  25000
#define FGENE 512
#define FDIS  256
#define CH    128
#define NE    150000

// ---------------- scratch (static device globals; no allocation) ----------------
__device__ float  g_xs[(size_t)NGENE * 512];
__device__ float  g_agg[(size_t)NGENE * CH];
__device__ float  g_ls[NGENE * 4];
__device__ float  g_ld[NGENE * 4];
__device__ float  g_logits[(NE + NGENE) * 4];
__device__ float  g_m[NGENE * 4];
__device__ float  g_denom[NGENE * 4];
__device__ float  g_wld[512];
__device__ double g_sum[CH];
__device__ double g_sumsq[CH];
__device__ float  g_scale[CH];
__device__ float  g_shift[CH];
__device__ __align__(256) __nv_bfloat16 g_ahi[(size_t)NGENE * 512];
__device__ __align__(256) __nv_bfloat16 g_alo[(size_t)NGENE * 512];
__device__ __align__(256) __nv_bfloat16 g_bthi[512 * 128];
__device__ __align__(256) __nv_bfloat16 g_btlo[512 * 128];

// ---------------- split conversions ----------------
__global__ void split_a_kernel(const float* __restrict__ A,
                               __nv_bfloat16* __restrict__ hi,
                               __nv_bfloat16* __restrict__ lo, int n4) {
    int i = blockIdx.x * blockDim.x + threadIdx.x;
    if (i >= n4) return;
    float4 v = ((const float4*)A)[i];
    __nv_bfloat16 h0 = __float2bfloat16(v.x), h1 = __float2bfloat16(v.y);
    __nv_bfloat16 h2 = __float2bfloat16(v.z), h3 = __float2bfloat16(v.w);
    __nv_bfloat16 l0 = __float2bfloat16(v.x - __bfloat162float(h0));
    __nv_bfloat16 l1 = __float2bfloat16(v.y - __bfloat162float(h1));
    __nv_bfloat16 l2 = __float2bfloat16(v.z - __bfloat162float(h2));
    __nv_bfloat16 l3 = __float2bfloat16(v.w - __bfloat162float(h3));
    ((__nv_bfloat162*)hi)[2 * i]     = __nv_bfloat162(h0, h1);
    ((__nv_bfloat162*)hi)[2 * i + 1] = __nv_bfloat162(h2, h3);
    ((__nv_bfloat162*)lo)[2 * i]     = __nv_bfloat162(l0, l1);
    ((__nv_bfloat162*)lo)[2 * i + 1] = __nv_bfloat162(l2, l3);
}

// B [K,N] fp32 -> Bt hi/lo [N,K] bf16 (transpose; tiny)
__global__ void split_bt_kernel(const float* __restrict__ B,
                                __nv_bfloat16* __restrict__ thi,
                                __nv_bfloat16* __restrict__ tlo, int K, int N) {
    int idx = blockIdx.x * blockDim.x + threadIdx.x;
    if (idx >= K * N) return;
    int k = idx / N, n = idx % N;
    float v = B[idx];
    __nv_bfloat16 h = __float2bfloat16(v);
    thi[(size_t)n * K + k] = h;
    tlo[(size_t)n * K + k] = __float2bfloat16(v - __bfloat162float(h));
}

// ---------------- split-bf16 GEMM via mma.sync + ldmatrix + cp.async ----------------
#define SST 40   // smem row stride in bf16 (80B): ldmatrix phases conflict-free

__device__ __forceinline__ void mma16816(float* c, const uint32_t* a,
                                         uint32_t b0, uint32_t b1) {
    asm volatile("mma.sync.aligned.m16n8k16.row.col.f32.bf16.bf16.f32 "
                 "{%0,%1,%2,%3}, {%4,%5,%6,%7}, {%8,%9}, {%0,%1,%2,%3};"
                 : "+f"(c[0]), "+f"(c[1]), "+f"(c[2]), "+f"(c[3])
                 : "r"(a[0]), "r"(a[1]), "r"(a[2]), "r"(a[3]), "r"(b0), "r"(b1));
}
__device__ __forceinline__ void ldmx4(uint32_t* r, uint32_t addr) {
    asm volatile("ldmatrix.sync.aligned.m8n8.x4.shared.b16 {%0,%1,%2,%3}, [%4];"
                 : "=r"(r[0]), "=r"(r[1]), "=r"(r[2]), "=r"(r[3]) : "r"(addr));
}
__device__ __forceinline__ void cp16(uint32_t saddr, const void* g, bool pred) {
    int sz = pred ? 16 : 0;
    asm volatile("cp.async.cg.shared.global [%0], [%1], 16, %2;"
                 :: "r"(saddr), "l"(g), "r"(sz));
}
__device__ __forceinline__ void cp_commit() {
    asm volatile("cp.async.commit_group;" ::: "memory");
}
template <int N_>
__device__ __forceinline__ void cp_wait() {
    asm volatile("cp.async.wait_group %0;" :: "n"(N_) : "memory");
}
__device__ __forceinline__ uint32_t smem_u32(const void* p) {
    uint32_t a;
    asm("{ .reg .u64 t; cvta.to.shared.u64 t, %1; cvt.u32.u64 %0, t; }" : "=r"(a) : "l"(p));
    return a;
}

// flags: bit0=bias, bit1=relu, bit2=fused ls (atomicAdd per-head <xs,a_s>)
__global__ __launch_bounds__(256, 2)
void gemm_mma_kernel(const __nv_bfloat16* __restrict__ Ahi, const __nv_bfloat16* __restrict__ Alo,
                     const __nv_bfloat16* __restrict__ Bthi, const __nv_bfloat16* __restrict__ Btlo,
                     const float* __restrict__ bias, const float* __restrict__ a_s,
                     float* __restrict__ C, int M, int N, int K, int flags)
{
    __shared__ __align__(16) __nv_bfloat16 smem[2][4][128 * SST];

    const int tid = threadIdx.x, wid = tid >> 5, lane = tid & 31;
    const int bm = blockIdx.y * 128, bn = blockIdx.x * 128;
    const int wm = (wid & 3) * 32, wn = (wid >> 2) * 64;
    const int lr = lane >> 2, lc = (lane & 3) * 2;
    const uint32_t sbase = smem_u32(&smem[0][0][0]);
    const uint32_t tilebytes = 128 * SST * 2;

    float acc[2][8][4];
#pragma unroll
    for (int mt = 0; mt < 2; mt++)
#pragma unroll
        for (int nt = 0; nt < 8; nt++)
#pragma unroll
            for (int j = 0; j < 4; j++) acc[mt][nt][j] = 0.f;

    // per-thread load coords (two halves)
    const int r0_ = tid >> 2, c8_ = (tid & 3) * 8;       // half 0: rows 0..63
    const int r1_ = r0_ + 64;                            // half 1: rows 64..127

    auto issue_stage = [&](int buf, int k0) {
#pragma unroll
        for (int h = 0; h < 2; h++) {
            const int r = h ? r1_ : r0_;
            const uint32_t soff = (uint32_t)(r * SST + c8_) * 2;
            const uint32_t sb = sbase + buf * 4 * tilebytes;
            const bool pa = (bm + r) < M;
            const int gr = pa ? (bm + r) : (M - 1);
            const size_t aoff = (size_t)gr * K + k0 + c8_;
            cp16(sb + soff, Ahi + aoff, pa);
            cp16(sb + tilebytes + soff, Alo + aoff, pa);
            const size_t boff = (size_t)(bn + r) * K + k0 + c8_;
            cp16(sb + 2 * tilebytes + soff, Bthi + boff, true);
            cp16(sb + 3 * tilebytes + soff, Btlo + boff, true);
        }
        cp_commit();
    };

    const int nt_chunks = K >> 5;
    issue_stage(0, 0);

    int buf = 0;
    for (int t = 0; t < nt_chunks; t++) {
        if (t + 1 < nt_chunks) {
            issue_stage(buf ^ 1, (t + 1) << 5);
            cp_wait<1>();
        } else {
            cp_wait<0>();
        }
        __syncthreads();

        const uint32_t sb = sbase + buf * 4 * tilebytes;
        const uint32_t sAh = sb, sAl = sb + tilebytes;
        const uint32_t sBh = sb + 2 * tilebytes, sBl = sb + 3 * tilebytes;

        // lane-address components
        const int arow = wm + (lane & 15);
        const int acol_off = (lane & 16) ? 8 : 0;
        const int brow = wn + (lane & 7) + ((lane & 16) ? 8 : 0);
        const int bcol_off = (lane & 8) ? 8 : 0;

#pragma unroll
        for (int ks = 0; ks < 2; ks++) {
            const int kb = ks * 16;
            uint32_t ah[2][4], al[2][4];
#pragma unroll
            for (int mt = 0; mt < 2; mt++) {
                const uint32_t aaddr = (uint32_t)(((arow + mt * 16) * SST) + kb + acol_off) * 2;
                ldmx4(ah[mt], sAh + aaddr);
                ldmx4(al[mt], sAl + aaddr);
            }
#pragma unroll
            for (int p = 0; p < 4; p++) {
                uint32_t bh[4], bl[4];
                const uint32_t baddr = (uint32_t)(((brow + p * 16) * SST) + kb + bcol_off) * 2;
                ldmx4(bh, sBh + baddr);
                ldmx4(bl, sBl + baddr);
#pragma unroll
                for (int sub = 0; sub < 2; sub++) {
                    const int nt = p * 2 + sub;
                    const uint32_t bh0 = bh[sub * 2], bh1 = bh[sub * 2 + 1];
                    const uint32_t bl0 = bl[sub * 2], bl1 = bl[sub * 2 + 1];
#pragma unroll
                    for (int mt = 0; mt < 2; mt++) {
                        mma16816(acc[mt][nt], ah[mt], bh0, bh1);
                        mma16816(acc[mt][nt], ah[mt], bl0, bl1);
                        mma16816(acc[mt][nt], al[mt], bh0, bh1);
                    }
                }
            }
        }
        __syncthreads();
        buf ^= 1;
    }

    // epilogue
#pragma unroll
    for (int mt = 0; mt < 2; mt++) {
        const int r0 = bm + wm + mt * 16 + lr;
#pragma unroll
        for (int nt = 0; nt < 8; nt++) {
            const int col = bn + wn + nt * 8 + lc;
            float2 v0 = make_float2(acc[mt][nt][0], acc[mt][nt][1]);
            float2 v1 = make_float2(acc[mt][nt][2], acc[mt][nt][3]);
            if (flags & 1) {
                float2 bb = *(const float2*)(bias + col);
                v0.x += bb.x; v0.y += bb.y; v1.x += bb.x; v1.y += bb.y;
            }
            if (flags & 2) {
                v0.x = fmaxf(v0.x, 0.f); v0.y = fmaxf(v0.y, 0.f);
                v1.x = fmaxf(v1.x, 0.f); v1.y = fmaxf(v1.y, 0.f);
            }
            if (r0 < M)     *(float2*)(C + (size_t)r0 * N + col) = v0;
            if (r0 + 8 < M) *(float2*)(C + (size_t)(r0 + 8) * N + col) = v1;
        }
    }
    if (flags & 4) {
        // fused ls: this CTA's 128 cols are exactly one head (N=512, bn aligned 128)
        const int head = bn >> 7;
#pragma unroll
        for (int mt = 0; mt < 2; mt++) {
            const int r0 = bm + wm + mt * 16 + lr;
            float p0 = 0.f, p8 = 0.f;
#pragma unroll
            for (int nt = 0; nt < 8; nt++) {
                const int c = wn + nt * 8 + lc;   // col within head
                const float a0 = a_s[head * 128 + c], a1 = a_s[head * 128 + c + 1];
                p0 += acc[mt][nt][0] * a0 + acc[mt][nt][1] * a1;
                p8 += acc[mt][nt][2] * a0 + acc[mt][nt][3] * a1;
            }
            if (r0 < M)     atomicAdd(&g_ls[r0 * 4 + head], p0);
            if (r0 + 8 < M) atomicAdd(&g_ls[(r0 + 8) * 4 + head], p8);
        }
    }
}

// ---------------- helpers ----------------
__device__ __forceinline__ void atomicMaxF(float* addr, float v) {
    if (v >= 0.f) atomicMax((int*)addr, __float_as_int(v));
    else          atomicMin((unsigned int*)addr, __float_as_uint(v));
}
__device__ __forceinline__ float leaky(float x) { return x > 0.f ? x : 0.2f * x; }

// ---------------- BatchNorm ----------------
__global__ void zero_stats_kernel() {
    int c = threadIdx.x;
    g_sum[c] = 0.0; g_sumsq[c] = 0.0;
}

__global__ void colsum_kernel(const float* __restrict__ h, int M) {
    int c = threadIdx.x;
    float s = 0.f, q = 0.f;
    for (int r = blockIdx.x; r < M; r += gridDim.x) {
        float v = h[(size_t)r * CH + c];
        s += v; q += v * v;
    }
    atomicAdd(&g_sum[c], (double)s);
    atomicAdd(&g_sumsq[c], (double)q);
}

__global__ void bn_params_kernel(const float* __restrict__ gamma,
                                 const float* __restrict__ beta, int M) {
    int c = threadIdx.x;
    double mu = g_sum[c] / M;
    double var = g_sumsq[c] / M - mu * mu;
    float sc = gamma[c] * rsqrtf((float)var + 1e-5f);
    g_scale[c] = sc;
    g_shift[c] = beta[c] - (float)mu * sc;
}

// optional fused bf16 split output (hi/lo may be null)
__global__ void bn_apply_kernel(float* __restrict__ h, int M,
                                __nv_bfloat16* __restrict__ hi,
                                __nv_bfloat16* __restrict__ lo) {
    int i = blockIdx.x * blockDim.x + threadIdx.x;
    if (i >= M * (CH / 4)) return;
    int c = (i & 31) * 4;
    float4 v = ((float4*)h)[i];
    v.x = v.x * g_scale[c + 0] + g_shift[c + 0];
    v.y = v.y * g_scale[c + 1] + g_shift[c + 1];
    v.z = v.z * g_scale[c + 2] + g_shift[c + 2];
    v.w = v.w * g_scale[c + 3] + g_shift[c + 3];
    ((float4*)h)[i] = v;
    if (hi) {
        __nv_bfloat16 h0 = __float2bfloat16(v.x), h1 = __float2bfloat16(v.y);
        __nv_bfloat16 h2 = __float2bfloat16(v.z), h3 = __float2bfloat16(v.w);
        ((__nv_bfloat162*)hi)[2 * i]     = __nv_bfloat162(h0, h1);
        ((__nv_bfloat162*)hi)[2 * i + 1] = __nv_bfloat162(h2, h3);
        ((__nv_bfloat162*)lo)[2 * i] =
            __nv_bfloat162(__float2bfloat16(v.x - __bfloat162float(h0)),
                           __float2bfloat16(v.y - __bfloat162float(h1)));
        ((__nv_bfloat162*)lo)[2 * i + 1] =
            __nv_bfloat162(__float2bfloat16(v.z - __bfloat162float(h2)),
                           __float2bfloat16(v.w - __bfloat162float(h3)));
    }
}

// ---------------- GAT pieces ----------------
__global__ void wld_kernel(const float* __restrict__ Wd, const float* __restrict__ ad) {
    int t = blockIdx.x * blockDim.x + threadIdx.x;
    if (t >= 512) return;
    int k = t >> 2, h = t & 3;
    float s = 0.f;
    for (int c = 0; c < 128; c++)
        s += Wd[(size_t)k * 512 + h * 128 + c] * ad[h * 128 + c];
    g_wld[k * 4 + h] = s;
}

__global__ void ld_kernel(const float* __restrict__ x, int N) {
    int w = (blockIdx.x * blockDim.x + threadIdx.x) >> 5;
    int lane = threadIdx.x & 31;
    if (w >= N) return;
    const float* row = x + (size_t)w * CH;
    float h0 = 0.f, h1 = 0.f, h2 = 0.f, h3 = 0.f;
#pragma unroll
    for (int j = 0; j < 4; j++) {
        int k = lane + 32 * j;
        float v = row[k];
        float4 wv = ((const float4*)g_wld)[k];
        h0 += v * wv.x; h1 += v * wv.y; h2 += v * wv.z; h3 += v * wv.w;
    }
#pragma unroll
    for (int off = 16; off > 0; off >>= 1) {
        h0 += __shfl_xor_sync(0xffffffffu, h0, off);
        h1 += __shfl_xor_sync(0xffffffffu, h1, off);
        h2 += __shfl_xor_sync(0xffffffffu, h2, off);
        h3 += __shfl_xor_sync(0xffffffffu, h3, off);
    }
    if (lane == 0) ((float4*)g_ld)[w] = make_float4(h0, h1, h2, h3);
}

// zero agg, m, denom, ls (ls is accumulated by the fused gemm epilogue)
__global__ void gat_init_kernel(int n_dst) {
    int stride = gridDim.x * blockDim.x;
    int start = blockIdx.x * blockDim.x + threadIdx.x;
    float ninf = __int_as_float(0xff800000);
    for (int i = start; i < n_dst * CH; i += stride) g_agg[i] = 0.f;
    for (int i = start; i < n_dst * 4; i += stride) {
        g_m[i] = ninf; g_denom[i] = 0.f; g_ls[i] = 0.f;
    }
}

__global__ void gat_pass1_kernel(const int* __restrict__ src, const int* __restrict__ dst,
                                 int E, int n_loop) {
    int e = blockIdx.x * blockDim.x + threadIdx.x;
    if (e >= E + n_loop) return;
    int s, d; bool mask;
    if (e < E) { s = src[e]; d = dst[e]; mask = (s != d); }
    else       { s = d = e - E; mask = true; }
    float4 a = ((const float4*)g_ls)[s];
    float4 b = ((const float4*)g_ld)[d];
    float l0 = leaky(a.x + b.x), l1 = leaky(a.y + b.y);
    float l2 = leaky(a.z + b.z), l3 = leaky(a.w + b.w);
    if (!mask) { l0 = l1 = l2 = l3 = -1e30f; }
    ((float4*)g_logits)[e] = make_float4(l0, l1, l2, l3);
    atomicMaxF(&g_m[d * 4 + 0], l0);
    atomicMaxF(&g_m[d * 4 + 1], l1);
    atomicMaxF(&g_m[d * 4 + 2], l2);
    atomicMaxF(&g_m[d * 4 + 3], l3);
}

__global__ void gat_pass2_kernel(const int* __restrict__ src, const int* __restrict__ dst,
                                 int E, int n_loop) {
    int e = blockIdx.x * blockDim.x + threadIdx.x;
    if (e >= E + n_loop) return;
    int d; bool mask;
    if (e < E) { int s = src[e]; d = dst[e]; mask = (s != d); }
    else       { d = e - E; mask = true; }
    float4 L = ((const float4*)g_logits)[e];
    float4 M4 = ((const float4*)g_m)[d];
    float p0 = mask ? expf(L.x - M4.x) : 0.f;
    float p1 = mask ? expf(L.y - M4.y) : 0.f;
    float p2 = mask ? expf(L.z - M4.z) : 0.f;
    float p3 = mask ? expf(L.w - M4.w) : 0.f;
    ((float4*)g_logits)[e] = make_float4(p0, p1, p2, p3);
    atomicAdd(&g_denom[d * 4 + 0], p0);
    atomicAdd(&g_denom[d * 4 + 1], p1);
    atomicAdd(&g_denom[d * 4 + 2], p2);
    atomicAdd(&g_denom[d * 4 + 3], p3);
}

__global__ void gat_pass3_kernel(const int* __restrict__ src, const int* __restrict__ dst,
                                 int E, int n_loop) {
    int w = (blockIdx.x * blockDim.x + threadIdx.x) >> 5;
    int lane = threadIdx.x & 31;
    if (w >= E + n_loop) return;
    int s, d;
    if (w < E) { s = src[w]; d = dst[w]; }
    else       { s = d = w - E; }
    float4 P = ((const float4*)g_logits)[w];
    float4 D = ((const float4*)g_denom)[d];
    float a0 = 0.25f * P.x / (D.x > 0.f ? D.x : 1.f);
    float a1 = 0.25f * P.y / (D.y > 0.f ? D.y : 1.f);
    float a2 = 0.25f * P.z / (D.z > 0.f ? D.z : 1.f);
    float a3 = 0.25f * P.w / (D.w > 0.f ? D.w : 1.f);
    const float4* xr = (const float4*)g_xs + (size_t)s * 128;
    float4 x0 = xr[lane], x1 = xr[32 + lane], x2 = xr[64 + lane], x3 = xr[96 + lane];
    float r0 = a0 * x0.x + a1 * x1.x + a2 * x2.x + a3 * x3.x;
    float r1 = a0 * x0.y + a1 * x1.y + a2 * x2.y + a3 * x3.y;
    float r2 = a0 * x0.z + a1 * x1.z + a2 * x2.z + a3 * x3.z;
    float r3 = a0 * x0.w + a1 * x1.w + a2 * x2.w + a3 * x3.w;
    float* out = g_agg + (size_t)d * CH + lane * 4;
    asm volatile("red.global.add.v4.f32 [%0], {%1, %2, %3, %4};"
                 :: "l"(out), "f"(r0), "f"(r1), "f"(r2), "f"(r3) : "memory");
}

// combine + optional fused split (for next relation's A operand)
__global__ void combine_kernel(float* __restrict__ gene, const float* __restrict__ bias,
                               __nv_bfloat16* __restrict__ hi,
                               __nv_bfloat16* __restrict__ lo) {
    int i = blockIdx.x * blockDim.x + threadIdx.x;   // over float4
    if (i >= NGENE * 32) return;
    int c = (i & 31) * 4;
    float4 v = ((float4*)gene)[i];
    float4 ag = ((const float4*)g_agg)[i];
    v.x += ag.x + bias[c + 0];
    v.y += ag.y + bias[c + 1];
    v.z += ag.z + bias[c + 2];
    v.w += ag.w + bias[c + 3];
    ((float4*)gene)[i] = v;
    if (hi) {
        __nv_bfloat16 h0 = __float2bfloat16(v.x), h1 = __float2bfloat16(v.y);
        __nv_bfloat16 h2 = __float2bfloat16(v.z), h3 = __float2bfloat16(v.w);
        ((__nv_bfloat162*)hi)[2 * i]     = __nv_bfloat162(h0, h1);
        ((__nv_bfloat162*)hi)[2 * i + 1] = __nv_bfloat162(h2, h3);
        ((__nv_bfloat162*)lo)[2 * i] =
            __nv_bfloat162(__float2bfloat16(v.x - __bfloat162float(h0)),
                           __float2bfloat16(v.y - __bfloat162float(h1)));
        ((__nv_bfloat162*)lo)[2 * i + 1] =
            __nv_bfloat162(__float2bfloat16(v.z - __bfloat162float(h2)),
                           __float2bfloat16(v.w - __bfloat162float(h3)));
    }
}

// ---------------- launch ----------------
extern "C" void kernel_launch(void* const* d_in, const int* in_sizes, int n_in,
                              void* d_out, int out_size) {
    const float* x_gene = (const float*)d_in[0];
    const float* x_dis  = (const float*)d_in[1];
    const int* e1_src = (const int*)d_in[2];
    const int* e1_dst = (const int*)d_in[3];
    const int* e2_src = (const int*)d_in[4];
    const int* e2_dst = (const int*)d_in[5];
    const float* Wg = (const float*)d_in[6];
    const float* bg = (const float*)d_in[7];
    const float* gg = (const float*)d_in[8];
    const float* betag = (const float*)d_in[9];
    const float* Wd = (const float*)d_in[10];
    const float* bd = (const float*)d_in[11];
    const float* gd = (const float*)d_in[12];
    const float* betad = (const float*)d_in[13];
    const float* W1s = (const float*)d_in[14];
    const float* W1d = (const float*)d_in[15];
    const float* a1s = (const float*)d_in[16];
    const float* a1d = (const float*)d_in[17];
    const float* b1  = (const float*)d_in[18];
    const float* W2s = (const float*)d_in[19];
    const float* W2d = (const float*)d_in[20];
    const float* a2s = (const float*)d_in[21];
    const float* a2d = (const float*)d_in[22];
    const float* b2  = (const float*)d_in[23];

    float* out_gene = (float*)d_out;
    float* out_dis  = (float*)d_out + (size_t)NGENE * CH;

    float* xs_ptr = nullptr;
    cudaGetSymbolAddress((void**)&xs_ptr, g_xs);
    __nv_bfloat16 *ahi, *alo, *bthi, *btlo;
    cudaGetSymbolAddress((void**)&ahi, g_ahi);
    cudaGetSymbolAddress((void**)&alo, g_alo);
    cudaGetSymbolAddress((void**)&bthi, g_bthi);
    cudaGetSymbolAddress((void**)&btlo, g_btlo);

    // ---- encode gene: relu(x@Wg+bg) -> BN ----
    zero_stats_kernel<<<1, 128>>>();
    split_a_kernel<<<(NGENE * FGENE / 4 + 255) / 256, 256>>>(x_gene, ahi, alo, NGENE * FGENE / 4);
    split_bt_kernel<<<(FGENE * CH + 255) / 256, 256>>>(Wg, bthi, btlo, FGENE, CH);
    gemm_mma_kernel<<<dim3(1, (NGENE + 127) / 128), 256>>>(
        ahi, alo, bthi, btlo, bg, nullptr, out_gene, NGENE, CH, FGENE, 3);
    colsum_kernel<<<512, 128>>>(out_gene, NGENE);
    bn_params_kernel<<<1, 128>>>(gg, betag, NGENE);
    bn_apply_kernel<<<(NGENE * 32 + 255) / 256, 256>>>(out_gene, NGENE, nullptr, nullptr);

    // ---- encode dis (fused: split of BN'd dis for rel1 A) ----
    zero_stats_kernel<<<1, 128>>>();
    split_a_kernel<<<(NDIS * FDIS / 4 + 255) / 256, 256>>>(x_dis, ahi, alo, NDIS * FDIS / 4);
    split_bt_kernel<<<(FDIS * CH + 255) / 256, 256>>>(Wd, bthi, btlo, FDIS, CH);
    gemm_mma_kernel<<<dim3(1, (NDIS + 127) / 128), 256>>>(
        ahi, alo, bthi, btlo, bd, nullptr, out_dis, NDIS, CH, FDIS, 3);
    colsum_kernel<<<512, 128>>>(out_dis, NDIS);
    bn_params_kernel<<<1, 128>>>(gd, betad, NDIS);
    bn_apply_kernel<<<(NDIS * 32 + 255) / 256, 256>>>(out_dis, NDIS, ahi, alo);

    // ---- relation 1: dis -> gene ----
    {
        const int E = NE, n_loop = NDIS, ET = E + n_loop;
        wld_kernel<<<2, 256>>>(W1d, a1d);
        split_bt_kernel<<<(CH * 512 + 255) / 256, 256>>>(W1s, bthi, btlo, CH, 512);
        gat_init_kernel<<<2048, 256>>>(NGENE);
        gemm_mma_kernel<<<dim3(4, (NDIS + 127) / 128), 256>>>(
            ahi, alo, bthi, btlo, nullptr, a1s, xs_ptr, NDIS, 512, CH, 4);
        ld_kernel<<<(NGENE + 7) / 8, 256>>>(out_gene, NGENE);
        gat_pass1_kernel<<<(ET + 255) / 256, 256>>>(e1_src, e1_dst, E, n_loop);
        gat_pass2_kernel<<<(ET + 255) / 256, 256>>>(e1_src, e1_dst, E, n_loop);
        gat_pass3_kernel<<<(ET + 7) / 8, 256>>>(e1_src, e1_dst, E, n_loop);
        combine_kernel<<<(NGENE * 32 + 255) / 256, 256>>>(out_gene, b1, ahi, alo);
    }

    // ---- relation 2: gene -> gene (updated gene; split produced by combine) ----
    {
        const int E = NE, n_loop = NGENE, ET = E + n_loop;
        wld_kernel<<<2, 256>>>(W2d, a2d);
        split_bt_kernel<<<(CH * 512 + 255) / 256, 256>>>(W2s, bthi, btlo, CH, 512);
        gat_init_kernel<<<2048, 256>>>(NGENE);
        gemm_mma_kernel<<<dim3(4, (NGENE + 127) / 128), 256>>>(
            ahi, alo, bthi, btlo, nullptr, a2s, xs_ptr, NGENE, 512, CH, 4);
        ld_kernel<<<(NGENE + 7) / 8, 256>>>(out_gene, NGENE);
        gat_pass1_kernel<<<(ET + 255) / 256, 256>>>(e2_src, e2_dst, E, n_loop);
        gat_pass2_kernel<<<(ET + 255) / 256, 256>>>(e2_src, e2_dst, E, n_loop);
        gat_pass3_kernel<<<(ET + 7) / 8, 256>>>(e2_src, e2_dst, E, n_loop);
        combine_kernel<<<(NGENE * 32 + 255) / 256, 256>>>(out_gene, b2, nullptr, nullptr);
    }
}

// round 6
// speedup vs baseline: 2.4296x; 1.0001x over previous
#include <cuda_runtime.h>
#include <cuda_bf16.h>
#include <math.h>
#include <cstdint>

#define NGENE 50000
#define NDIS  25000
#define FGENE 512
#define FDIS  256
#define CH    128
#define NE    150000

// ---------------- scratch (static device globals; no allocation) ----------------
__device__ float  g_xs[(size_t)NGENE * 512];
__device__ float  g_agg[(size_t)NGENE * CH];
__device__ float  g_ls[NGENE * 4];
__device__ float  g_ld[NGENE * 4];
__device__ float  g_logits[(NE + NGENE) * 4];
__device__ float  g_denom[NGENE * 4];
__device__ float  g_wld[512];
__device__ double g_sum[CH];
__device__ double g_sumsq[CH];
__device__ float  g_scale[CH];
__device__ float  g_shift[CH];
__device__ __align__(256) __nv_bfloat16 g_bthi[512 * 128];
__device__ __align__(256) __nv_bfloat16 g_btlo[512 * 128];

// ---------------- small helpers ----------------
__device__ __forceinline__ float leaky(float x) { return x > 0.f ? x : 0.2f * x; }
__device__ __forceinline__ uint32_t smem_u32(const void* p) {
    uint32_t a;
    asm("{ .reg .u64 t; cvta.to.shared.u64 t, %1; cvt.u32.u64 %0, t; }" : "=r"(a) : "l"(p));
    return a;
}
__device__ __forceinline__ void mma16816(float* c, const uint32_t* a,
                                         uint32_t b0, uint32_t b1) {
    asm volatile("mma.sync.aligned.m16n8k16.row.col.f32.bf16.bf16.f32 "
                 "{%0,%1,%2,%3}, {%4,%5,%6,%7}, {%8,%9}, {%0,%1,%2,%3};"
                 : "+f"(c[0]), "+f"(c[1]), "+f"(c[2]), "+f"(c[3])
                 : "r"(a[0]), "r"(a[1]), "r"(a[2]), "r"(a[3]), "r"(b0), "r"(b1));
}
__device__ __forceinline__ void ldmx4(uint32_t* r, uint32_t addr) {
    asm volatile("ldmatrix.sync.aligned.m8n8.x4.shared.b16 {%0,%1,%2,%3}, [%4];"
                 : "=r"(r[0]), "=r"(r[1]), "=r"(r[2]), "=r"(r[3]) : "r"(addr));
}
__device__ __forceinline__ void cp16(uint32_t saddr, const void* g) {
    asm volatile("cp.async.cg.shared.global [%0], [%1], 16;" :: "r"(saddr), "l"(g));
}
__device__ __forceinline__ void cp_commit() {
    asm volatile("cp.async.commit_group;" ::: "memory");
}
template <int N_>
__device__ __forceinline__ void cp_wait() {
    asm volatile("cp.async.wait_group %0;" :: "n"(N_) : "memory");
}
__device__ __forceinline__ uint32_t pack_bf2(float x, float y) {
    __nv_bfloat162 t(__float2bfloat16(x), __float2bfloat16(y));
    return *(uint32_t*)&t;
}

// B [K,N] fp32 -> Bt hi/lo [N,K] bf16 (transpose; tiny)
__global__ void split_bt_kernel(const float* __restrict__ B,
                                __nv_bfloat16* __restrict__ thi,
                                __nv_bfloat16* __restrict__ tlo, int K, int N) {
    int idx = blockIdx.x * blockDim.x + threadIdx.x;
    if (idx >= K * N) return;
    int k = idx / N, n = idx % N;
    float v = B[idx];
    __nv_bfloat16 h = __float2bfloat16(v);
    thi[(size_t)n * K + k] = h;
    tlo[(size_t)n * K + k] = __float2bfloat16(v - __bfloat162float(h));
}

// ---------------- split-bf16 GEMM: fp32 A (inline split) + bf16 Bt ----------------
// flags: 1=bias, 2=relu, 4=fused ls (per-head <row, a_s> -> g_ls), 8=fused colsum
#define SST 40

__global__ __launch_bounds__(256, 2)
void gemm_mma_kernel(const float* __restrict__ A,
                     const __nv_bfloat16* __restrict__ Bthi,
                     const __nv_bfloat16* __restrict__ Btlo,
                     const float* __restrict__ bias, const float* __restrict__ a_s,
                     float* __restrict__ C, int M, int N, int K, int flags)
{
    __shared__ __align__(16) __nv_bfloat16 smem[2][4][128 * SST];  // Ah, Al, Bh, Bl
    __shared__ float cs[128], cq[128];

    const int tid = threadIdx.x, wid = tid >> 5, lane = tid & 31;
    const int bm = blockIdx.y * 128, bn = blockIdx.x * 128;
    const int wm = (wid & 3) * 32, wn = (wid >> 2) * 64;
    const int lr = lane >> 2, lc = (lane & 3) * 2;
    const uint32_t sbase = smem_u32(&smem[0][0][0]);
    const uint32_t tilebytes = 128 * SST * 2;

    if ((flags & 8) && tid < 128) { cs[tid] = 0.f; cq[tid] = 0.f; }

    float acc[2][8][4];
#pragma unroll
    for (int mt = 0; mt < 2; mt++)
#pragma unroll
        for (int nt = 0; nt < 8; nt++)
#pragma unroll
            for (int j = 0; j < 4; j++) acc[mt][nt][j] = 0.f;

    // B cp.async coords: 128 rows x 32 cols bf16, 2 halves
    const int br_ = tid >> 2, bc8_ = (tid & 3) * 8;
    // A LDG coords: 128 rows x 32 cols fp32: thread -> row tid>>1, 16 cols
    const int ar = tid >> 1, ac = (tid & 1) * 16;
    const int agr = (bm + ar < M) ? (bm + ar) : (M - 1);

    float av[16];

    auto ldgA = [&](int k0) {
        const float4* p = (const float4*)(A + (size_t)agr * K + k0 + ac);
        float4 v0 = p[0], v1 = p[1], v2 = p[2], v3 = p[3];
        av[0] = v0.x; av[1] = v0.y; av[2] = v0.z; av[3] = v0.w;
        av[4] = v1.x; av[5] = v1.y; av[6] = v1.z; av[7] = v1.w;
        av[8] = v2.x; av[9] = v2.y; av[10] = v2.z; av[11] = v2.w;
        av[12] = v3.x; av[13] = v3.y; av[14] = v3.z; av[15] = v3.w;
    };
    auto stsA = [&](int buf) {
        uint32_t hi[8], lo[8];
#pragma unroll
        for (int j = 0; j < 8; j++) {
            float x0 = av[2 * j], x1 = av[2 * j + 1];
            __nv_bfloat16 h0 = __float2bfloat16(x0), h1 = __float2bfloat16(x1);
            hi[j] = pack_bf2(x0, x1);
            lo[j] = pack_bf2(x0 - __bfloat162float(h0), x1 - __bfloat162float(h1));
        }
        char* base = (char*)&smem[buf][0][0];
        const uint32_t off = (uint32_t)(ar * SST + ac) * 2;
        *(uint4*)(base + off)      = make_uint4(hi[0], hi[1], hi[2], hi[3]);
        *(uint4*)(base + off + 16) = make_uint4(hi[4], hi[5], hi[6], hi[7]);
        char* basel = (char*)&smem[buf][1][0];
        *(uint4*)(basel + off)      = make_uint4(lo[0], lo[1], lo[2], lo[3]);
        *(uint4*)(basel + off + 16) = make_uint4(lo[4], lo[5], lo[6], lo[7]);
    };
    auto issueB = [&](int buf, int k0) {
#pragma unroll
        for (int h = 0; h < 2; h++) {
            const int r = br_ + h * 64;
            const uint32_t soff = (uint32_t)(r * SST + bc8_) * 2;
            const uint32_t sb = sbase + buf * 4 * tilebytes + 2 * tilebytes + soff;
            const size_t boff = (size_t)(bn + r) * K + k0 + bc8_;
            cp16(sb, Bthi + boff);
            cp16(sb + tilebytes, Btlo + boff);
        }
        cp_commit();
    };

    const int nch = K >> 5;
    ldgA(0); issueB(0, 0); stsA(0);

    int buf = 0;
    for (int t = 0; t < nch; t++) {
        const bool has = (t + 1 < nch);
        if (has) {
            ldgA((t + 1) << 5);
            issueB(buf ^ 1, (t + 1) << 5);
            cp_wait<1>();
        } else {
            cp_wait<0>();
        }
        __syncthreads();

        const uint32_t sb = sbase + buf * 4 * tilebytes;
        const uint32_t sAh = sb, sAl = sb + tilebytes;
        const uint32_t sBh = sb + 2 * tilebytes, sBl = sb + 3 * tilebytes;

        const int arow = wm + (lane & 15);
        const int acol_off = (lane & 16) ? 8 : 0;
        const int brow = wn + (lane & 7) + ((lane & 16) ? 8 : 0);
        const int bcol_off = (lane & 8) ? 8 : 0;

#pragma unroll
        for (int ks = 0; ks < 2; ks++) {
            const int kb = ks * 16;
            uint32_t ah[2][4], al[2][4];
#pragma unroll
            for (int mt = 0; mt < 2; mt++) {
                const uint32_t aaddr = (uint32_t)(((arow + mt * 16) * SST) + kb + acol_off) * 2;
                ldmx4(ah[mt], sAh + aaddr);
                ldmx4(al[mt], sAl + aaddr);
            }
#pragma unroll
            for (int p = 0; p < 4; p++) {
                uint32_t bh[4], bl[4];
                const uint32_t baddr = (uint32_t)(((brow + p * 16) * SST) + kb + bcol_off) * 2;
                ldmx4(bh, sBh + baddr);
                ldmx4(bl, sBl + baddr);
#pragma unroll
                for (int sub = 0; sub < 2; sub++) {
                    const int nt = p * 2 + sub;
                    const uint32_t bh0 = bh[sub * 2], bh1 = bh[sub * 2 + 1];
                    const uint32_t bl0 = bl[sub * 2], bl1 = bl[sub * 2 + 1];
#pragma unroll
                    for (int mt = 0; mt < 2; mt++) {
                        mma16816(acc[mt][nt], ah[mt], bh0, bh1);
                        mma16816(acc[mt][nt], ah[mt], bl0, bl1);
                        mma16816(acc[mt][nt], al[mt], bh0, bh1);
                    }
                }
            }
        }
        __syncthreads();
        if (has) stsA(buf ^ 1);
        buf ^= 1;
    }

    // ---------------- epilogue ----------------
#pragma unroll
    for (int mt = 0; mt < 2; mt++) {
        const int r0 = bm + wm + mt * 16 + lr;
        const bool ok0 = r0 < M, ok1 = (r0 + 8) < M;
#pragma unroll
        for (int nt = 0; nt < 8; nt++) {
            const int col = bn + wn + nt * 8 + lc;
            float2 v0 = make_float2(acc[mt][nt][0], acc[mt][nt][1]);
            float2 v1 = make_float2(acc[mt][nt][2], acc[mt][nt][3]);
            if (flags & 1) {
                float2 bb = *(const float2*)(bias + col);
                v0.x += bb.x; v0.y += bb.y; v1.x += bb.x; v1.y += bb.y;
            }
            if (flags & 2) {
                v0.x = fmaxf(v0.x, 0.f); v0.y = fmaxf(v0.y, 0.f);
                v1.x = fmaxf(v1.x, 0.f); v1.y = fmaxf(v1.y, 0.f);
            }
            if (ok0) *(float2*)(C + (size_t)r0 * N + col) = v0;
            if (ok1) *(float2*)(C + (size_t)(r0 + 8) * N + col) = v1;
            if (flags & 8) {  // fused colsum (encode: N=128, bn=0)
                float s0 = (ok0 ? v0.x : 0.f) + (ok1 ? v1.x : 0.f);
                float s1 = (ok0 ? v0.y : 0.f) + (ok1 ? v1.y : 0.f);
                float q0 = (ok0 ? v0.x * v0.x : 0.f) + (ok1 ? v1.x * v1.x : 0.f);
                float q1 = (ok0 ? v0.y * v0.y : 0.f) + (ok1 ? v1.y * v1.y : 0.f);
                const int cc = wn + nt * 8 + lc;
                atomicAdd(&cs[cc], s0); atomicAdd(&cs[cc + 1], s1);
                atomicAdd(&cq[cc], q0); atomicAdd(&cq[cc + 1], q1);
            }
            // store back (for fused-ls pass below)
            acc[mt][nt][0] = v0.x; acc[mt][nt][1] = v0.y;
            acc[mt][nt][2] = v1.x; acc[mt][nt][3] = v1.y;
        }
    }
    if (flags & 4) {  // fused ls: CTA's 128 cols = one head (N=512)
        const int head = bn >> 7;
#pragma unroll
        for (int mt = 0; mt < 2; mt++) {
            const int r0 = bm + wm + mt * 16 + lr;
            float p0 = 0.f, p8 = 0.f;
#pragma unroll
            for (int nt = 0; nt < 8; nt++) {
                const int c = wn + nt * 8 + lc;
                const float a0 = a_s[head * 128 + c], a1 = a_s[head * 128 + c + 1];
                p0 += acc[mt][nt][0] * a0 + acc[mt][nt][1] * a1;
                p8 += acc[mt][nt][2] * a0 + acc[mt][nt][3] * a1;
            }
            if (r0 < M)     atomicAdd(&g_ls[r0 * 4 + head], p0);
            if (r0 + 8 < M) atomicAdd(&g_ls[(r0 + 8) * 4 + head], p8);
        }
    }
    if (flags & 8) {
        __syncthreads();
        if (tid < 128) {
            atomicAdd(&g_sum[tid], (double)cs[tid]);
            atomicAdd(&g_sumsq[tid], (double)cq[tid]);
        }
    }
}

// ---------------- BatchNorm ----------------
__global__ void zero_stats_kernel() {
    int c = threadIdx.x;
    g_sum[c] = 0.0; g_sumsq[c] = 0.0;
}

__global__ void bn_params_kernel(const float* __restrict__ gamma,
                                 const float* __restrict__ beta, int M) {
    int c = threadIdx.x;
    double mu = g_sum[c] / M;
    double var = g_sumsq[c] / M - mu * mu;
    float sc = gamma[c] * rsqrtf((float)var + 1e-5f);
    g_scale[c] = sc;
    g_shift[c] = beta[c] - (float)mu * sc;
}

// BN apply; fuse_ld: also compute g_ld (warp-per-row reduce against g_wld)
__global__ void bn_apply_kernel(float* __restrict__ h, int M, int fuse_ld) {
    int i = blockIdx.x * blockDim.x + threadIdx.x;   // over float4s; one warp = one row
    if (i >= M * (CH / 4)) return;
    int c = (i & 31) * 4;
    float4 v = ((float4*)h)[i];
    v.x = v.x * g_scale[c + 0] + g_shift[c + 0];
    v.y = v.y * g_scale[c + 1] + g_shift[c + 1];
    v.z = v.z * g_scale[c + 2] + g_shift[c + 2];
    v.w = v.w * g_scale[c + 3] + g_shift[c + 3];
    ((float4*)h)[i] = v;
    if (fuse_ld) {
        float4 w0 = ((const float4*)g_wld)[c + 0];
        float4 w1 = ((const float4*)g_wld)[c + 1];
        float4 w2 = ((const float4*)g_wld)[c + 2];
        float4 w3 = ((const float4*)g_wld)[c + 3];
        float p0 = v.x * w0.x + v.y * w1.x + v.z * w2.x + v.w * w3.x;
        float p1 = v.x * w0.y + v.y * w1.y + v.z * w2.y + v.w * w3.y;
        float p2 = v.x * w0.z + v.y * w1.z + v.z * w2.z + v.w * w3.z;
        float p3 = v.x * w0.w + v.y * w1.w + v.z * w2.w + v.w * w3.w;
#pragma unroll
        for (int off = 16; off > 0; off >>= 1) {
            p0 += __shfl_xor_sync(0xffffffffu, p0, off);
            p1 += __shfl_xor_sync(0xffffffffu, p1, off);
            p2 += __shfl_xor_sync(0xffffffffu, p2, off);
            p3 += __shfl_xor_sync(0xffffffffu, p3, off);
        }
        if ((i & 31) == 0) ((float4*)g_ld)[i >> 5] = make_float4(p0, p1, p2, p3);
    }
}

// ---------------- GAT pieces ----------------
__global__ void wld_kernel(const float* __restrict__ Wd, const float* __restrict__ ad) {
    int t = blockIdx.x * blockDim.x + threadIdx.x;
    if (t >= 512) return;
    int k = t >> 2, h = t & 3;
    float s = 0.f;
    for (int c = 0; c < 128; c++)
        s += Wd[(size_t)k * 512 + h * 128 + c] * ad[h * 128 + c];
    g_wld[k * 4 + h] = s;
}

__global__ void gat_init_kernel(int n_dst) {
    int stride = gridDim.x * blockDim.x;
    int start = blockIdx.x * blockDim.x + threadIdx.x;
    for (int i = start; i < n_dst * CH; i += stride) g_agg[i] = 0.f;
    for (int i = start; i < n_dst * 4; i += stride) { g_denom[i] = 0.f; g_ls[i] = 0.f; }
}

// merged pass1+2: p = exp(leaky(ls[s]+ld[d])) * mask ; segment-sum denom
__global__ void gat_edge_kernel(const int* __restrict__ src, const int* __restrict__ dst,
                                int E, int n_loop) {
    int e = blockIdx.x * blockDim.x + threadIdx.x;
    if (e >= E + n_loop) return;
    int s, d; bool mask;
    if (e < E) { s = src[e]; d = dst[e]; mask = (s != d); }
    else       { s = d = e - E; mask = true; }
    float4 a = ((const float4*)g_ls)[s];
    float4 b = ((const float4*)g_ld)[d];
    float p0 = mask ? expf(leaky(a.x + b.x)) : 0.f;
    float p1 = mask ? expf(leaky(a.y + b.y)) : 0.f;
    float p2 = mask ? expf(leaky(a.z + b.z)) : 0.f;
    float p3 = mask ? expf(leaky(a.w + b.w)) : 0.f;
    ((float4*)g_logits)[e] = make_float4(p0, p1, p2, p3);
    atomicAdd(&g_denom[d * 4 + 0], p0);
    atomicAdd(&g_denom[d * 4 + 1], p1);
    atomicAdd(&g_denom[d * 4 + 2], p2);
    atomicAdd(&g_denom[d * 4 + 3], p3);
}

__global__ void gat_pass3_kernel(const int* __restrict__ src, const int* __restrict__ dst,
                                 int E, int n_loop) {
    int w = (blockIdx.x * blockDim.x + threadIdx.x) >> 5;
    int lane = threadIdx.x & 31;
    if (w >= E + n_loop) return;
    int s, d;
    if (w < E) { s = src[w]; d = dst[w]; }
    else       { s = d = w - E; }
    float4 P = ((const float4*)g_logits)[w];
    float4 D = ((const float4*)g_denom)[d];
    float a0 = 0.25f * P.x / (D.x > 0.f ? D.x : 1.f);
    float a1 = 0.25f * P.y / (D.y > 0.f ? D.y : 1.f);
    float a2 = 0.25f * P.z / (D.z > 0.f ? D.z : 1.f);
    float a3 = 0.25f * P.w / (D.w > 0.f ? D.w : 1.f);
    const float4* xr = (const float4*)g_xs + (size_t)s * 128;
    float4 x0 = xr[lane], x1 = xr[32 + lane], x2 = xr[64 + lane], x3 = xr[96 + lane];
    float r0 = a0 * x0.x + a1 * x1.x + a2 * x2.x + a3 * x3.x;
    float r1 = a0 * x0.y + a1 * x1.y + a2 * x2.y + a3 * x3.y;
    float r2 = a0 * x0.z + a1 * x1.z + a2 * x2.z + a3 * x3.z;
    float r3 = a0 * x0.w + a1 * x1.w + a2 * x2.w + a3 * x3.w;
    float* out = g_agg + (size_t)d * CH + lane * 4;
    asm volatile("red.global.add.v4.f32 [%0], {%1, %2, %3, %4};"
                 :: "l"(out), "f"(r0), "f"(r1), "f"(r2), "f"(r3) : "memory");
}

// combine; fuse_ld: also compute g_ld for next relation (warp-per-row)
__global__ void combine_kernel(float* __restrict__ gene, const float* __restrict__ bias,
                               int fuse_ld) {
    int i = blockIdx.x * blockDim.x + threadIdx.x;   // over float4s; one warp = one row
    if (i >= NGENE * 32) return;
    int c = (i & 31) * 4;
    float4 v = ((float4*)gene)[i];
    float4 ag = ((const float4*)g_agg)[i];
    v.x += ag.x + bias[c + 0];
    v.y += ag.y + bias[c + 1];
    v.z += ag.z + bias[c + 2];
    v.w += ag.w + bias[c + 3];
    ((float4*)gene)[i] = v;
    if (fuse_ld) {
        float4 w0 = ((const float4*)g_wld)[c + 0];
        float4 w1 = ((const float4*)g_wld)[c + 1];
        float4 w2 = ((const float4*)g_wld)[c + 2];
        float4 w3 = ((const float4*)g_wld)[c + 3];
        float p0 = v.x * w0.x + v.y * w1.x + v.z * w2.x + v.w * w3.x;
        float p1 = v.x * w0.y + v.y * w1.y + v.z * w2.y + v.w * w3.y;
        float p2 = v.x * w0.z + v.y * w1.z + v.z * w2.z + v.w * w3.z;
        float p3 = v.x * w0.w + v.y * w1.w + v.z * w2.w + v.w * w3.w;
#pragma unroll
        for (int off = 16; off > 0; off >>= 1) {
            p0 += __shfl_xor_sync(0xffffffffu, p0, off);
            p1 += __shfl_xor_sync(0xffffffffu, p1, off);
            p2 += __shfl_xor_sync(0xffffffffu, p2, off);
            p3 += __shfl_xor_sync(0xffffffffu, p3, off);
        }
        if ((i & 31) == 0) ((float4*)g_ld)[i >> 5] = make_float4(p0, p1, p2, p3);
    }
}

// ---------------- launch ----------------
extern "C" void kernel_launch(void* const* d_in, const int* in_sizes, int n_in,
                              void* d_out, int out_size) {
    const float* x_gene = (const float*)d_in[0];
    const float* x_dis  = (const float*)d_in[1];
    const int* e1_src = (const int*)d_in[2];
    const int* e1_dst = (const int*)d_in[3];
    const int* e2_src = (const int*)d_in[4];
    const int* e2_dst = (const int*)d_in[5];
    const float* Wg = (const float*)d_in[6];
    const float* bg = (const float*)d_in[7];
    const float* gg = (const float*)d_in[8];
    const float* betag = (const float*)d_in[9];
    const float* Wd = (const float*)d_in[10];
    const float* bd = (const float*)d_in[11];
    const float* gd = (const float*)d_in[12];
    const float* betad = (const float*)d_in[13];
    const float* W1s = (const float*)d_in[14];
    const float* W1d = (const float*)d_in[15];
    const float* a1s = (const float*)d_in[16];
    const float* a1d = (const float*)d_in[17];
    const float* b1  = (const float*)d_in[18];
    const float* W2s = (const float*)d_in[19];
    const float* W2d = (const float*)d_in[20];
    const float* a2s = (const float*)d_in[21];
    const float* a2d = (const float*)d_in[22];
    const float* b2  = (const float*)d_in[23];

    float* out_gene = (float*)d_out;
    float* out_dis  = (float*)d_out + (size_t)NGENE * CH;

    float* xs_ptr = nullptr;
    cudaGetSymbolAddress((void**)&xs_ptr, g_xs);
    __nv_bfloat16 *bthi, *btlo;
    cudaGetSymbolAddress((void**)&bthi, g_bthi);
    cudaGetSymbolAddress((void**)&btlo, g_btlo);

    // ---- encode gene: relu(x@Wg+bg) -> BN (colsum fused into GEMM) ----
    zero_stats_kernel<<<1, 128>>>();
    split_bt_kernel<<<(FGENE * CH + 255) / 256, 256>>>(Wg, bthi, btlo, FGENE, CH);
    gemm_mma_kernel<<<dim3(1, (NGENE + 127) / 128), 256>>>(
        x_gene, bthi, btlo, bg, nullptr, out_gene, NGENE, CH, FGENE, 1 | 2 | 8);
    bn_params_kernel<<<1, 128>>>(gg, betag, NGENE);
    wld_kernel<<<2, 256>>>(W1d, a1d);                                  // for fused ld
    bn_apply_kernel<<<(NGENE * 32 + 255) / 256, 256>>>(out_gene, NGENE, 1);

    // ---- encode dis ----
    zero_stats_kernel<<<1, 128>>>();
    split_bt_kernel<<<(FDIS * CH + 255) / 256, 256>>>(Wd, bthi, btlo, FDIS, CH);
    gemm_mma_kernel<<<dim3(1, (NDIS + 127) / 128), 256>>>(
        x_dis, bthi, btlo, bd, nullptr, out_dis, NDIS, CH, FDIS, 1 | 2 | 8);
    bn_params_kernel<<<1, 128>>>(gd, betad, NDIS);
    bn_apply_kernel<<<(NDIS * 32 + 255) / 256, 256>>>(out_dis, NDIS, 0);

    // ---- relation 1: dis -> gene ----
    {
        const int E = NE, n_loop = NDIS, ET = E + n_loop;
        split_bt_kernel<<<(CH * 512 + 255) / 256, 256>>>(W1s, bthi, btlo, CH, 512);
        gat_init_kernel<<<2048, 256>>>(NGENE);
        gemm_mma_kernel<<<dim3(4, (NDIS + 127) / 128), 256>>>(
            out_dis, bthi, btlo, nullptr, a1s, xs_ptr, NDIS, 512, CH, 4);
        gat_edge_kernel<<<(ET + 255) / 256, 256>>>(e1_src, e1_dst, E, n_loop);
        gat_pass3_kernel<<<(ET + 7) / 8, 256>>>(e1_src, e1_dst, E, n_loop);
        wld_kernel<<<2, 256>>>(W2d, a2d);                              // for fused ld
        combine_kernel<<<(NGENE * 32 + 255) / 256, 256>>>(out_gene, b1, 1);
    }

    // ---- relation 2: gene -> gene ----
    {
        const int E = NE, n_loop = NGENE, ET = E + n_loop;
        split_bt_kernel<<<(CH * 512 + 255) / 256, 256>>>(W2s, bthi, btlo, CH, 512);
        gat_init_kernel<<<2048, 256>>>(NGENE);
        gemm_mma_kernel<<<dim3(4, (NGENE + 127) / 128), 256>>>(
            out_gene, bthi, btlo, nullptr, a2s, xs_ptr, NGENE, 512, CH, 4);
        gat_edge_kernel<<<(ET + 255) / 256, 256>>>(e2_src, e2_dst, E, n_loop);
        gat_pass3_kernel<<<(ET + 7) / 8, 256>>>(e2_src, e2_dst, E, n_loop);
        combine_kernel<<<(NGENE * 32 + 255) / 256, 256>>>(out_gene, b2, 0);
    }
}